// round 15
// baseline (speedup 1.0000x reference)
#include <cuda_runtime.h>
#include <cuda_bf16.h>
#include <cuda_fp16.h>
#include <math.h>

#define NROWS 131072
#define RB128 (NROWS/128)   // 1024
#define MARGIN 1.0f
#define CAND_CAP 32

// ---------------- scratch (device globals; no allocation allowed) ----------------
__device__ float g_z   [(size_t)NROWS * 256];
__device__ __nv_bfloat16 g_qbf [(size_t)NROWS * 256];
__device__ __nv_bfloat16 g_dbA [(size_t)NROWS * 512];
__device__ __nv_bfloat16 g_dbB [(size_t)NROWS * 512];
__device__ __half g_spin[(size_t)NROWS * 128];    // state split2 fp16, Kp=64
__device__ __half g_sp1 [(size_t)NROWS * 1024];   // h1 split2, Kp=512
__device__ __half g_sp2 [(size_t)NROWS * 1024];   // h2 split2, Kp=512
__device__ __half g_wsp1[512 * 128];
__device__ __half g_wsp2[512 * 1024];
__device__ __half g_wsp3[256 * 1024];
__device__ __nv_bfloat16 g_wt1[512 * 256];
__device__ __nv_bfloat16 g_wt2[512 * 512];
__device__ __nv_bfloat16 g_wt3[56 * 512];
__device__ __nv_bfloat16 g_cbh[2 * 1024 * 256];
__device__ float g_cn  [2 * 1024];
__device__ float g_l1p [RB128];
__device__ float g_vqp [RB128];

// ---------------- helpers ----------------
__device__ __forceinline__ unsigned smaddr(const void* p) {
    return (unsigned)__cvta_generic_to_shared(p);
}
__device__ __forceinline__ void cpa16(unsigned dst, const void* src, int sz) {
    asm volatile("cp.async.cg.shared.global [%0], [%1], 16, %2;\n"
                 :: "r"(dst), "l"(src), "r"(sz));
}
#define CP_COMMIT asm volatile("cp.async.commit_group;\n")
template<int N> __device__ __forceinline__ void cp_wait() {
    asm volatile("cp.async.wait_group %0;\n" :: "n"(N));
}
__device__ __forceinline__ void mma_bf16(float* c, const unsigned* a, unsigned b0, unsigned b1) {
    asm volatile(
        "mma.sync.aligned.m16n8k16.row.col.f32.bf16.bf16.f32 "
        "{%0,%1,%2,%3}, {%4,%5,%6,%7}, {%8,%9}, {%0,%1,%2,%3};\n"
        : "+f"(c[0]), "+f"(c[1]), "+f"(c[2]), "+f"(c[3])
        : "r"(a[0]), "r"(a[1]), "r"(a[2]), "r"(a[3]), "r"(b0), "r"(b1));
}
__device__ __forceinline__ void mma_f16(float* c, const unsigned* a, unsigned b0, unsigned b1) {
    asm volatile(
        "mma.sync.aligned.m16n8k16.row.col.f32.f16.f16.f32 "
        "{%0,%1,%2,%3}, {%4,%5,%6,%7}, {%8,%9}, {%0,%1,%2,%3};\n"
        : "+f"(c[0]), "+f"(c[1]), "+f"(c[2]), "+f"(c[3])
        : "r"(a[0]), "r"(a[1]), "r"(a[2]), "r"(a[3]), "r"(b0), "r"(b1));
}
__device__ __forceinline__ void ldsm4(unsigned& r0, unsigned& r1, unsigned& r2, unsigned& r3,
                                      unsigned addr) {
    asm volatile("ldmatrix.sync.aligned.m8n8.x4.shared.b16 {%0,%1,%2,%3}, [%4];"
                 : "=r"(r0), "=r"(r1), "=r"(r2), "=r"(r3) : "r"(addr));
}
__device__ __forceinline__ unsigned fford(float f) {
    unsigned u = __float_as_uint(f);
    return (u & 0x80000000u) ? ~u : (u | 0x80000000u);
}
__device__ __forceinline__ float iford(unsigned u) {
    return __uint_as_float((u & 0x80000000u) ? (u ^ 0x80000000u) : ~u);
}
__device__ __forceinline__ void split2h(float v, __half& h0, __half& h1)
{
    h0 = __float2half_rn(v);
    float r = v - __half2float(h0);
    h1 = __float2half_rn(r);
}
#define SWZ(r, cb) ((unsigned)((r) * 128 + ((cb) ^ (((r) & 7) << 4))))

// ================= unified mma.sync GEMM engine (col-fast grid) =================
// MODE 0 = plain bf16 (3-stage pipeline). MODE 1 = fp16 split2 with tile-dedup
// schedule: per kc, pairs (A1*B0),(A0*B0),(A0*B1) load only 4 distinct tiles
// into a 6-tile ring (vs 6 loads in pair-major order).
// OUT: 0 = f32 (+bias), 1 = relu+split2 fp16 planes, 2 = relu+bf16, 3 = L1 partials.
template<int KP, int MODE, int OUT>
__global__ __launch_bounds__(256) void mgemm(
    const void* __restrict__ Av, const void* __restrict__ BTv,
    const float* __restrict__ bias, void* __restrict__ Cv, int M, int KpN,
    const float* __restrict__ Xref, float* __restrict__ part)
{
    constexpr int ROWB = (MODE == 1) ? KP * 4 : KP * 2;     // bytes per A/BT row
    constexpr int NKCB = KP / 64;                           // 128B chunks per pass
    const unsigned char* A  = (const unsigned char*)Av;
    const unsigned char* BT = (const unsigned char*)BTv;

    extern __shared__ __align__(16) char dynsm[];
    __shared__ float s_red[256];

    const int tid = threadIdx.x;
    const int lane = tid & 31, wid = tid >> 5;
    const int wm = wid & 3, wn = wid >> 2;
    const int row0 = blockIdx.y * 128;
    const int col0 = blockIdx.x * 128;

    unsigned dynb = (smaddr(dynsm) + 1023u) & ~1023u;

    float acc[2][8][4];
    #pragma unroll
    for (int a = 0; a < 2; a++)
        #pragma unroll
        for (int b = 0; b < 8; b++)
            #pragma unroll
            for (int c = 0; c < 4; c++) acc[a][b][c] = 0.f;

    const int lrow = ((lane >> 3) & 1) * 8 + (lane & 7);
    const int lcb  = (lane >= 16) ? 16 : 0;

    if (MODE == 1) {
        // ---- tile-dedup split schedule ----
        constexpr int NLOAD = 4 * NKCB;
        constexpr int NSTEP = 3 * NKCB;
        unsigned tb[6];
        #pragma unroll
        for (int s = 0; s < 6; s++) tb[s] = dynb + s * 16384u;

        auto load_tile = [&](int li) {
            int kc = li >> 2, slot = li & 3;
            unsigned dst = tb[li % 6];
            if ((slot & 1) == 0) {            // A: slot0 = plane1, slot2 = plane0
                int aoffB = (slot == 0 ? KP * 2 : 0) + kc * 128;
                #pragma unroll
                for (int i = 0; i < 4; i++) {
                    int ch = tid + 256 * i;
                    int r = ch >> 3, gg = ch & 7;
                    cpa16(dst + SWZ(r, gg * 16),
                          A + (size_t)(row0 + r) * ROWB + aoffB + gg * 16, 16);
                }
            } else {                          // B: slot1 = plane0, slot3 = plane1
                int boffB = (slot == 3 ? KP * 2 : 0) + kc * 128;
                #pragma unroll
                for (int i = 0; i < 4; i++) {
                    int ch = tid + 256 * i;
                    int r = ch >> 3, gg = ch & 7;
                    int br = col0 + r;
                    int ok = (br < M);
                    const unsigned char* src = BT + (size_t)(ok ? br : 0) * ROWB + boffB + gg * 16;
                    cpa16(dst + SWZ(r, gg * 16), src, ok ? 16 : 0);
                }
            }
            CP_COMMIT;
        };
        int issued = 0;
        auto issue_to = [&](int t) {
            if (t > NLOAD) t = NLOAD;
            for (; issued < t; issued++) load_tile(issued);
        };
        issue_to(3);

        for (int s = 0; s < NSTEP; s++) {
            const int kc = s / 3, m = s - 3 * kc;
            if (s == NSTEP - 1)      cp_wait<0>();
            else if (m == 2)         cp_wait<2>();
            else                     cp_wait<1>();
            __syncthreads();
            {
                int s2 = s + 2;
                int kc2 = s2 / 3, m2 = s2 - 3 * kc2;
                issue_to(4 * kc2 + (m2 == 0 ? 2 : (m2 == 1 ? 3 : 4)));
            }
            const unsigned Aw = (m == 0) ? tb[(4 * kc) % 6]     : tb[(4 * kc + 2) % 6];
            const unsigned Bw = (m == 2) ? tb[(4 * kc + 3) % 6] : tb[(4 * kc + 1) % 6];
            #pragma unroll
            for (int kki = 0; kki < 4; kki++) {
                const int kb = kki * 32;
                unsigned a[2][4];
                #pragma unroll
                for (int mf = 0; mf < 2; mf++) {
                    int r = wm * 32 + mf * 16 + lrow;
                    ldsm4(a[mf][0], a[mf][1], a[mf][2], a[mf][3], Aw + SWZ(r, kb + lcb));
                }
                unsigned bq[4][4];
                #pragma unroll
                for (int h = 0; h < 4; h++) {
                    int r = wn * 64 + h * 16 + lrow;
                    ldsm4(bq[h][0], bq[h][1], bq[h][2], bq[h][3], Bw + SWZ(r, kb + lcb));
                }
                #pragma unroll
                for (int nf = 0; nf < 8; nf++) {
                    int h = nf >> 1, o = nf & 1;
                    mma_f16(acc[0][nf], a[0], bq[h][o], bq[h][o + 2]);
                    mma_f16(acc[1][nf], a[1], bq[h][o], bq[h][o + 2]);
                }
            }
        }
    } else {
        // ---- plain bf16, proven 3-stage pipeline ----
        constexpr int NCH = NKCB;
        unsigned Ab[3], Bb[3];
        #pragma unroll
        for (int s = 0; s < 3; s++) { Ab[s] = dynb + s * 32768u; Bb[s] = Ab[s] + 16384u; }

        auto fill = [&](int s, int c) {
            int offB = c * 128;
            #pragma unroll
            for (int i = 0; i < 4; i++) {
                int ch = tid + 256 * i;
                int r = ch >> 3, gg = ch & 7;
                cpa16(Ab[s] + SWZ(r, gg * 16),
                      A + (size_t)(row0 + r) * ROWB + offB + gg * 16, 16);
            }
            #pragma unroll
            for (int i = 0; i < 4; i++) {
                int ch = tid + 256 * i;
                int r = ch >> 3, gg = ch & 7;
                int br = col0 + r;
                int ok = (br < M);
                const unsigned char* src = BT + (size_t)(ok ? br : 0) * ROWB + offB + gg * 16;
                cpa16(Bb[s] + SWZ(r, gg * 16), src, ok ? 16 : 0);
            }
        };

        fill(0, 0); CP_COMMIT;
        if (NCH > 1) { fill(1, 1); CP_COMMIT; }

        for (int c = 0; c < NCH; c++) {
            const int s = c % 3;
            if (c + 1 < NCH) cp_wait<1>(); else cp_wait<0>();
            __syncthreads();
            if (c + 2 < NCH) { fill((c + 2) % 3, c + 2); CP_COMMIT; }

            const unsigned Aw = Ab[s], Bw = Bb[s];
            #pragma unroll
            for (int kki = 0; kki < 4; kki++) {
                const int kb = kki * 32;
                unsigned a[2][4];
                #pragma unroll
                for (int mf = 0; mf < 2; mf++) {
                    int r = wm * 32 + mf * 16 + lrow;
                    ldsm4(a[mf][0], a[mf][1], a[mf][2], a[mf][3], Aw + SWZ(r, kb + lcb));
                }
                unsigned bq[4][4];
                #pragma unroll
                for (int h = 0; h < 4; h++) {
                    int r = wn * 64 + h * 16 + lrow;
                    ldsm4(bq[h][0], bq[h][1], bq[h][2], bq[h][3], Bw + SWZ(r, kb + lcb));
                }
                #pragma unroll
                for (int nf = 0; nf < 8; nf++) {
                    int h = nf >> 1, o = nf & 1;
                    mma_bf16(acc[0][nf], a[0], bq[h][o], bq[h][o + 2]);
                    mma_bf16(acc[1][nf], a[1], bq[h][o], bq[h][o + 2]);
                }
            }
        }
    }

    const int g = lane >> 2, q2 = (lane & 3) * 2;
    if (OUT == 0) {
        float* C = (float*)Cv;
        #pragma unroll
        for (int mf = 0; mf < 2; mf++) {
            int r1 = row0 + wm * 32 + mf * 16 + g;
            #pragma unroll
            for (int nf = 0; nf < 8; nf++) {
                int cc = col0 + wn * 64 + nf * 8 + q2;
                float2 o0 = make_float2(acc[mf][nf][0] + bias[cc], acc[mf][nf][1] + bias[cc + 1]);
                float2 o1 = make_float2(acc[mf][nf][2] + bias[cc], acc[mf][nf][3] + bias[cc + 1]);
                *(float2*)(C + (size_t)r1 * M + cc) = o0;
                *(float2*)(C + (size_t)(r1 + 8) * M + cc) = o1;
            }
        }
    } else if (OUT == 1) {
        __half* C = (__half*)Cv;
        const size_t strd = 2 * (size_t)KpN;
        #pragma unroll
        for (int mf = 0; mf < 2; mf++) {
            int r1 = row0 + wm * 32 + mf * 16 + g;
            #pragma unroll
            for (int nf = 0; nf < 8; nf++) {
                int cc = col0 + wn * 64 + nf * 8 + q2;
                #pragma unroll
                for (int half = 0; half < 2; half++) {
                    int r = r1 + (half ? 8 : 0);
                    float v0 = fmaxf(acc[mf][nf][2 * half + 0] + bias[cc], 0.f);
                    float v1 = fmaxf(acc[mf][nf][2 * half + 1] + bias[cc + 1], 0.f);
                    __half a0, a1, b0, b1;
                    split2h(v0, a0, a1);
                    split2h(v1, b0, b1);
                    __half* base = C + (size_t)r * strd + cc;
                    __half2 p0; p0.x = a0; p0.y = b0;
                    __half2 p1; p1.x = a1; p1.y = b1;
                    *(__half2*)(base)       = p0;
                    *(__half2*)(base + KpN) = p1;
                }
            }
        }
    } else if (OUT == 2) {
        __nv_bfloat16* C = (__nv_bfloat16*)Cv;
        #pragma unroll
        for (int mf = 0; mf < 2; mf++) {
            int r1 = row0 + wm * 32 + mf * 16 + g;
            #pragma unroll
            for (int nf = 0; nf < 8; nf++) {
                int cc = col0 + wn * 64 + nf * 8 + q2;
                float v0 = fmaxf(acc[mf][nf][0] + bias[cc], 0.f);
                float v1 = fmaxf(acc[mf][nf][1] + bias[cc + 1], 0.f);
                float v2 = fmaxf(acc[mf][nf][2] + bias[cc], 0.f);
                float v3 = fmaxf(acc[mf][nf][3] + bias[cc + 1], 0.f);
                __nv_bfloat162 h0; h0.x = __float2bfloat16(v0); h0.y = __float2bfloat16(v1);
                __nv_bfloat162 h1; h1.x = __float2bfloat16(v2); h1.y = __float2bfloat16(v3);
                *(__nv_bfloat162*)(C + (size_t)r1 * M + cc) = h0;
                *(__nv_bfloat162*)(C + (size_t)(r1 + 8) * M + cc) = h1;
            }
        }
    } else {
        float s = 0.f;
        #pragma unroll
        for (int mf = 0; mf < 2; mf++) {
            int r1 = row0 + wm * 32 + mf * 16 + g;
            #pragma unroll
            for (int nf = 0; nf < 8; nf++) {
                int cc = col0 + wn * 64 + nf * 8 + q2;
                #pragma unroll
                for (int e = 0; e < 4; e++) {
                    int c = cc + (e & 1);
                    int r = r1 + (e >= 2 ? 8 : 0);
                    if (c < M) {
                        float v = acc[mf][nf][e] + bias[c];
                        s += fabsf(Xref[(size_t)r * M + c] - v);
                    }
                }
            }
        }
        __syncthreads();
        s_red[tid] = s;
        __syncthreads();
        #pragma unroll
        for (int off = 128; off > 0; off >>= 1) {
            if (tid < off) s_red[tid] += s_red[tid + off];
            __syncthreads();
        }
        if (tid == 0) part[blockIdx.y] = s_red[0];
    }
}

// ================= fused prep kernel =================
__global__ __launch_bounds__(256) void prep_k(
    const float* __restrict__ state,
    const float* __restrict__ ew1, const float* __restrict__ ew2, const float* __restrict__ ew3,
    const float* __restrict__ dw1, const float* __restrict__ dw2, const float* __restrict__ dw3,
    const float* __restrict__ cbk,
    __half* __restrict__ spin, __half* __restrict__ wsp1, __half* __restrict__ wsp2,
    __half* __restrict__ wsp3,
    __nv_bfloat16* __restrict__ wt1, __nv_bfloat16* __restrict__ wt2,
    __nv_bfloat16* __restrict__ wt3, __nv_bfloat16* __restrict__ cbh,
    float* __restrict__ cnp)
{
    long gid = (long)blockIdx.x * 256 + threadIdx.x;

    if (gid < 8388608L) {
        long n = gid >> 6; int k = (int)(gid & 63);
        float v = (k < 56) ? state[n * 56 + k] : 0.f;
        __half h0, h1; split2h(v, h0, h1);
        __half* d = spin + n * 128;
        d[k] = h0; d[64 + k] = h1;
        return;
    }
    gid -= 8388608L;
    if (gid < 524288) { cbh[gid] = __float2bfloat16(cbk[gid]); return; }
    gid -= 524288;
    if (gid < 131072) {
        int k = (int)(gid / 512), m = (int)(gid % 512);
        wt1[(size_t)m * 256 + k] = __float2bfloat16(dw1[gid]);
        return;
    }
    gid -= 131072;
    if (gid < 262144) {
        int k = (int)(gid / 512), m = (int)(gid % 512);
        wt2[(size_t)m * 512 + k] = __float2bfloat16(dw2[gid]);
        return;
    }
    gid -= 262144;
    if (gid < 28672) {
        int k = (int)(gid / 56), m = (int)(gid % 56);
        wt3[(size_t)m * 512 + k] = __float2bfloat16(dw3[gid]);
        return;
    }
    gid -= 28672;
    if (gid < 32768) {
        int m = (int)(gid / 64), k = (int)(gid % 64);
        float v = (k < 56) ? ew1[(size_t)k * 512 + m] : 0.f;
        __half h0, h1; split2h(v, h0, h1);
        __half* d = wsp1 + (size_t)m * 128;
        d[k] = h0; d[64 + k] = h1;
        return;
    }
    gid -= 32768;
    if (gid < 262144) {
        int m = (int)(gid / 512), k = (int)(gid % 512);
        float v = ew2[(size_t)k * 512 + m];
        __half h0, h1; split2h(v, h0, h1);
        __half* d = wsp2 + (size_t)m * 1024;
        d[k] = h0; d[512 + k] = h1;
        return;
    }
    gid -= 262144;
    if (gid < 131072) {
        int m = (int)(gid / 512), k = (int)(gid % 512);
        float v = ew3[(size_t)k * 256 + m];
        __half h0, h1; split2h(v, h0, h1);
        __half* d = wsp3 + (size_t)m * 1024;
        d[k] = h0; d[512 + k] = h1;
        return;
    }
    gid -= 131072;
    if (gid < 65536) {
        int w = (int)(gid >> 5);
        int lane = (int)(gid & 31);
        const float* c = cbk + (size_t)w * 256;
        float s = 0.f;
        #pragma unroll
        for (int k = lane; k < 256; k += 32) s = fmaf(c[k], c[k], s);
        #pragma unroll
        for (int off = 16; off > 0; off >>= 1) s += __shfl_xor_sync(0xffffffff, s, off);
        if (lane == 0) cnp[w] = 0.5f * s;
    }
}
#define PREP_THREADS (8388608L + 524288 + 131072 + 262144 + 28672 + 32768 + 262144 + 131072 + 65536)
#define PREP_BLOCKS  ((int)((PREP_THREADS + 255) / 256))

// ================= fused residual-VQ (unchanged) =================
#define VQ_SMEM (216068 + 1024)

__device__ __forceinline__ void vq_score8(
    unsigned AsB, unsigned BsB, char* smc,
    const __nv_bfloat16* __restrict__ cbh, const float* __restrict__ cn,
    int* cand, unsigned* rowmin, int* cnt,
    int tid, int lane, int wid, int wm, int wn, int g, int q2, int lrow, int lcb)
{
    #pragma unroll
    for (int i = 0; i < 16; i++) {
        int ch = tid + 256 * i;
        int r = ch >> 5, gg = ch & 31;
        cpa16(BsB + (unsigned)(gg >> 3) * 16384u + SWZ(r, (gg & 7) * 16),
              cbh + (size_t)r * 256 + gg * 8, 16);
    }
    CP_COMMIT;

    for (int t = 0; t < 8; t++) {
        if (t < 7) {
            unsigned stb = BsB + (unsigned)((t + 1) & 1) * 65536u;
            #pragma unroll
            for (int i = 0; i < 16; i++) {
                int ch = tid + 256 * i;
                int r = ch >> 5, gg = ch & 31;
                cpa16(stb + (unsigned)(gg >> 3) * 16384u + SWZ(r, (gg & 7) * 16),
                      cbh + (size_t)((t + 1) * 128 + r) * 256 + gg * 8, 16);
            }
            CP_COMMIT;
            cp_wait<1>();
        } else {
            cp_wait<0>();
        }
        __syncthreads();

        float acc[2][8][4];
        #pragma unroll
        for (int a = 0; a < 2; a++)
            #pragma unroll
            for (int b = 0; b < 8; b++)
                #pragma unroll
                for (int c = 0; c < 4; c++) acc[a][b][c] = 0.f;

        const unsigned Bst = BsB + (unsigned)(t & 1) * 65536u;
        #pragma unroll
        for (int kk = 0; kk < 256; kk += 16) {
            int kb = kk >> 6;
            int kloc = (kk & 63) * 2;
            unsigned a[2][4];
            #pragma unroll
            for (int mf = 0; mf < 2; mf++) {
                int r = wm * 32 + mf * 16 + lrow;
                ldsm4(a[mf][0], a[mf][1], a[mf][2], a[mf][3],
                      AsB + (unsigned)kb * 16384u + SWZ(r, kloc + lcb));
            }
            unsigned bq[4][4];
            #pragma unroll
            for (int h = 0; h < 4; h++) {
                int r = wn * 64 + h * 16 + lrow;
                ldsm4(bq[h][0], bq[h][1], bq[h][2], bq[h][3],
                      Bst + (unsigned)kb * 16384u + SWZ(r, kloc + lcb));
            }
            #pragma unroll
            for (int nf = 0; nf < 8; nf++) {
                int h = nf >> 1, o = nf & 1;
                mma_bf16(acc[0][nf], a[0], bq[h][o], bq[h][o + 2]);
                mma_bf16(acc[1][nf], a[1], bq[h][o], bq[h][o + 2]);
            }
        }

        #pragma unroll
        for (int mf = 0; mf < 2; mf++) {
            int r1 = wm * 32 + mf * 16 + g;
            float m1 = 1e30f, m2 = 1e30f;
            #pragma unroll
            for (int nf = 0; nf < 8; nf++) {
                int cl = wn * 64 + nf * 8 + q2;
                float cn0 = __ldg(cn + t * 128 + cl);
                float cn1 = __ldg(cn + t * 128 + cl + 1);
                float s0 = cn0 - acc[mf][nf][0];
                float s1 = cn1 - acc[mf][nf][1];
                float s2 = cn0 - acc[mf][nf][2];
                float s3 = cn1 - acc[mf][nf][3];
                acc[mf][nf][0] = s0; acc[mf][nf][1] = s1;
                acc[mf][nf][2] = s2; acc[mf][nf][3] = s3;
                m1 = fminf(m1, fminf(s0, s1));
                m2 = fminf(m2, fminf(s2, s3));
            }
            atomicMin(&rowmin[r1], fford(m1));
            atomicMin(&rowmin[r1 + 8], fford(m2));
        }
        __syncthreads();
        #pragma unroll
        for (int mf = 0; mf < 2; mf++) {
            int r1 = wm * 32 + mf * 16 + g;
            float thr1 = iford(rowmin[r1]) + MARGIN;
            float thr2 = iford(rowmin[r1 + 8]) + MARGIN;
            #pragma unroll
            for (int nf = 0; nf < 8; nf++) {
                int code = t * 128 + wn * 64 + nf * 8 + q2;
                #pragma unroll
                for (int e = 0; e < 4; e++) {
                    float s = acc[mf][nf][e];
                    int r = (e >= 2) ? (r1 + 8) : r1;
                    float thr = (e >= 2) ? thr2 : thr1;
                    if (s <= thr) {
                        int p = atomicAdd(&cnt[r], 1);
                        if (p < CAND_CAP) cand[r * CAND_CAP + p] = code + (e & 1);
                    }
                }
            }
        }
        __syncthreads();
    }
}

__device__ __forceinline__ void vq_rescue(
    const float rr[8], const float* __restrict__ cbf, const float* __restrict__ cn,
    const int* cand, int row, int cv, int lane, int& bc_out)
{
    float bv = 1e30f; int bc = 0;
    if (cv <= CAND_CAP) {
        for (int i = 0; i < cv; i++) {
            int c = cand[row * CAND_CAP + i];
            const float* cp = cbf + (size_t)c * 256 + lane * 8;
            float d = 0.f;
            #pragma unroll
            for (int e = 0; e < 8; e++) d = fmaf(rr[e], __ldg(cp + e), d);
            #pragma unroll
            for (int off = 16; off > 0; off >>= 1) d += __shfl_xor_sync(0xffffffff, d, off);
            float s = __ldg(cn + c) - d;
            if (s < bv || (s == bv && c < bc)) { bv = s; bc = c; }
        }
    } else {
        for (int c = 0; c < 1024; c++) {
            const float* cp = cbf + (size_t)c * 256 + lane * 8;
            float d = 0.f;
            #pragma unroll
            for (int e = 0; e < 8; e++) d = fmaf(rr[e], __ldg(cp + e), d);
            #pragma unroll
            for (int off = 16; off > 0; off >>= 1) d += __shfl_xor_sync(0xffffffff, d, off);
            float s = __ldg(cn + c) - d;
            if (s < bv || (s == bv && c < bc)) { bv = s; bc = c; }
        }
    }
    bc_out = bc;
}

__global__ __launch_bounds__(256) void vqfused_k(
    const float* __restrict__ zg, const __nv_bfloat16* __restrict__ cbh,
    const float* __restrict__ cbf, const float* __restrict__ cn,
    float* __restrict__ codes_out, __nv_bfloat16* __restrict__ qbf,
    float* __restrict__ vqpart)
{
    extern __shared__ __align__(16) char sm[];
    unsigned dynb = (smaddr(sm) + 1023u) & ~1023u;
    char* smc = sm + (int)(dynb - smaddr(sm));
    const unsigned AsB = dynb;
    const unsigned BsB = dynb + 65536u;
    int*      cand   = (int*)     (smc + 196608);
    unsigned* rowmin = (unsigned*)(smc + 212992);
    int*      cnt    = (int*)     (smc + 213504);
    int*      ch0    = (int*)     (smc + 214016);
    int*      ch1    = (int*)     (smc + 214528);
    float*    red    = (float*)   (smc + 215040);
    float*    s0p    = (float*)   (smc + 216064);

    const int tid = threadIdx.x;
    const int lane = tid & 31, wid = tid >> 5;
    const int wm = wid & 3, wn = wid >> 2;
    const size_t row0 = (size_t)blockIdx.x * 128;
    const int g = lane >> 2, q2 = (lane & 3) * 2;
    const int lrow = ((lane >> 3) & 1) * 8 + (lane & 7);
    const int lcb  = (lane >= 16) ? 16 : 0;

    const __nv_bfloat16* cbh1 = cbh + 1024 * 256;
    const float* cbf1 = cbf + 1024 * 256;
    const float* cn1  = cn + 1024;

    if (tid < 128) { rowmin[tid] = 0xFFFFFFFFu; cnt[tid] = 0; }

    #pragma unroll
    for (int i = 0; i < 32; i++) {
        int e = tid + 256 * i;
        int r = e >> 6, c4 = e & 63;
        float4 v = *(const float4*)(zg + (row0 + r) * 256 + 4 * c4);
        __nv_bfloat162 h0; h0.x = __float2bfloat16(v.x); h0.y = __float2bfloat16(v.y);
        __nv_bfloat162 h1; h1.x = __float2bfloat16(v.z); h1.y = __float2bfloat16(v.w);
        uint2 p; p.x = *(unsigned*)&h0; p.y = *(unsigned*)&h1;
        int kb = c4 >> 4;
        unsigned off = (unsigned)kb * 16384u + (unsigned)r * 128u
                     + (((unsigned)((c4 * 8) & 127)) ^ (((unsigned)r & 7u) << 4));
        *(uint2*)(smc + off) = p;
    }
    __syncthreads();

    vq_score8(AsB, BsB, smc, cbh, cn, cand, rowmin, cnt,
              tid, lane, wid, wm, wn, g, q2, lrow, lcb);

    for (int j = 0; j < 16; j++) {
        int row = wid + 8 * j;
        const float* rp = zg + (row0 + row) * 256 + lane * 8;
        float4 u = *(const float4*)rp;
        float4 v = *(const float4*)(rp + 4);
        float rr[8] = {u.x, u.y, u.z, u.w, v.x, v.y, v.z, v.w};
        int bc;
        vq_rescue(rr, cbf, cn, cand, row, cnt[row], lane, bc);
        if (lane == 0) {
            ch0[row] = bc;
            codes_out[(row0 + row) * 2 + 0] = (float)bc;
        }
    }
    __syncthreads();

    float vac = 0.f;
    #pragma unroll
    for (int i = 0; i < 32; i++) {
        int e = tid + 256 * i;
        int r = e >> 6, c4 = e & 63;
        int c = ch0[r];
        size_t off = (row0 + r) * 256 + 4 * c4;
        float4 cvv = *(const float4*)(cbf + (size_t)c * 256 + 4 * c4);
        float4 zv  = *(const float4*)(zg + off);
        float4 dv = make_float4(zv.x - cvv.x, zv.y - cvv.y, zv.z - cvv.z, zv.w - cvv.w);
        vac += dv.x * dv.x + dv.y * dv.y + dv.z * dv.z + dv.w * dv.w;
        __nv_bfloat162 h0; h0.x = __float2bfloat16(dv.x); h0.y = __float2bfloat16(dv.y);
        __nv_bfloat162 h1; h1.x = __float2bfloat16(dv.z); h1.y = __float2bfloat16(dv.w);
        uint2 p; p.x = *(unsigned*)&h0; p.y = *(unsigned*)&h1;
        int kb = c4 >> 4;
        unsigned soff = (unsigned)kb * 16384u + (unsigned)r * 128u
                      + (((unsigned)((c4 * 8) & 127)) ^ (((unsigned)r & 7u) << 4));
        *(uint2*)(smc + soff) = p;
    }
    red[tid] = vac;
    __syncthreads();
    #pragma unroll
    for (int off = 128; off > 0; off >>= 1) {
        if (tid < off) red[tid] += red[tid + off];
        __syncthreads();
    }
    if (tid == 0) *s0p = red[0];
    if (tid < 128) { rowmin[tid] = 0xFFFFFFFFu; cnt[tid] = 0; }
    __syncthreads();

    vq_score8(AsB, BsB, smc, cbh1, cn1, cand, rowmin, cnt,
              tid, lane, wid, wm, wn, g, q2, lrow, lcb);

    for (int j = 0; j < 16; j++) {
        int row = wid + 8 * j;
        const float* rp = zg + (row0 + row) * 256 + lane * 8;
        const float* cp0 = cbf + (size_t)ch0[row] * 256 + lane * 8;
        float4 u = *(const float4*)rp;
        float4 v = *(const float4*)(rp + 4);
        float4 a = *(const float4*)cp0;
        float4 b = *(const float4*)(cp0 + 4);
        float rr[8] = {u.x - a.x, u.y - a.y, u.z - a.z, u.w - a.w,
                       v.x - b.x, v.y - b.y, v.z - b.z, v.w - b.w};
        int bc;
        vq_rescue(rr, cbf1, cn1, cand, row, cnt[row], lane, bc);
        if (lane == 0) {
            ch1[row] = bc;
            codes_out[(row0 + row) * 2 + 1] = (float)bc;
        }
    }
    __syncthreads();

    vac = 0.f;
    #pragma unroll
    for (int i = 0; i < 32; i++) {
        int e = tid + 256 * i;
        int r = e >> 6, c4 = e & 63;
        int c = ch1[r], c0 = ch0[r];
        size_t off = (row0 + r) * 256 + 4 * c4;
        float4 cvv = *(const float4*)(cbf1 + (size_t)c * 256 + 4 * c4);
        float4 q0v = *(const float4*)(cbf + (size_t)c0 * 256 + 4 * c4);
        float4 zv  = *(const float4*)(zg + off);
        float4 rv = make_float4(zv.x - q0v.x, zv.y - q0v.y, zv.z - q0v.z, zv.w - q0v.w);
        float4 dv = make_float4(rv.x - cvv.x, rv.y - cvv.y, rv.z - cvv.z, rv.w - cvv.w);
        vac += dv.x * dv.x + dv.y * dv.y + dv.z * dv.z + dv.w * dv.w;
        float4 sv = make_float4(q0v.x + cvv.x, q0v.y + cvv.y, q0v.z + cvv.z, q0v.w + cvv.w);
        __nv_bfloat162 h0; h0.x = __float2bfloat16(sv.x); h0.y = __float2bfloat16(sv.y);
        __nv_bfloat162 h1; h1.x = __float2bfloat16(sv.z); h1.y = __float2bfloat16(sv.w);
        *(__nv_bfloat162*)(qbf + off) = h0;
        *(__nv_bfloat162*)(qbf + off + 2) = h1;
    }
    red[tid] = vac;
    __syncthreads();
    #pragma unroll
    for (int off = 128; off > 0; off >>= 1) {
        if (tid < off) red[tid] += red[tid + off];
        __syncthreads();
    }
    if (tid == 0) vqpart[blockIdx.x] = *s0p + red[0];
}

// ================= final deterministic loss combine =================
__global__ __launch_bounds__(256) void final_k(
    const float* __restrict__ l1p, const float* __restrict__ vqp, float* __restrict__ out)
{
    __shared__ float sa[256], sb[256];
    float a = 0.f, b = 0.f;
    for (int i = threadIdx.x; i < RB128; i += 256) { a += l1p[i]; b += vqp[i]; }
    sa[threadIdx.x] = a; sb[threadIdx.x] = b;
    __syncthreads();
    #pragma unroll
    for (int off = 128; off > 0; off >>= 1) {
        if (threadIdx.x < off) {
            sa[threadIdx.x] += sa[threadIdx.x + off];
            sb[threadIdx.x] += sb[threadIdx.x + off];
        }
        __syncthreads();
    }
    if (threadIdx.x == 0) {
        float enc_loss = sa[0] / (131072.0f * 56.0f);
        float vq_loss  = sb[0] / (131072.0f * 256.0f);
        out[0] = enc_loss + 5.0f * vq_loss;
    }
}

// ================= launch =================
extern "C" void kernel_launch(void* const* d_in, const int* in_sizes, int n_in,
                              void* d_out, int out_size)
{
    const float* state = (const float*)d_in[0];
    const float* ew1 = (const float*)d_in[1];
    const float* eb1 = (const float*)d_in[2];
    const float* ew2 = (const float*)d_in[3];
    const float* eb2 = (const float*)d_in[4];
    const float* ew3 = (const float*)d_in[5];
    const float* eb3 = (const float*)d_in[6];
    const float* dw1 = (const float*)d_in[7];
    const float* db1 = (const float*)d_in[8];
    const float* dw2 = (const float*)d_in[9];
    const float* db2 = (const float*)d_in[10];
    const float* dw3 = (const float*)d_in[11];
    const float* db3 = (const float*)d_in[12];
    const float* cbk = (const float*)d_in[13];
    float* out = (float*)d_out;

    float *zb, *cnp, *l1p, *vqp;
    __nv_bfloat16 *qbf, *dbA, *dbB, *cbh, *wt1, *wt2, *wt3;
    __half *spin, *sp1, *sp2, *wsp1, *wsp2, *wsp3;
    cudaGetSymbolAddress((void**)&zb,   g_z);
    cudaGetSymbolAddress((void**)&qbf,  g_qbf);
    cudaGetSymbolAddress((void**)&dbA,  g_dbA);
    cudaGetSymbolAddress((void**)&dbB,  g_dbB);
    cudaGetSymbolAddress((void**)&spin, g_spin);
    cudaGetSymbolAddress((void**)&sp1,  g_sp1);
    cudaGetSymbolAddress((void**)&sp2,  g_sp2);
    cudaGetSymbolAddress((void**)&wsp1, g_wsp1);
    cudaGetSymbolAddress((void**)&wsp2, g_wsp2);
    cudaGetSymbolAddress((void**)&wsp3, g_wsp3);
    cudaGetSymbolAddress((void**)&wt1,  g_wt1);
    cudaGetSymbolAddress((void**)&wt2,  g_wt2);
    cudaGetSymbolAddress((void**)&wt3,  g_wt3);
    cudaGetSymbolAddress((void**)&cbh,  g_cbh);
    cudaGetSymbolAddress((void**)&cnp,  g_cn);
    cudaGetSymbolAddress((void**)&l1p,  g_l1p);
    cudaGetSymbolAddress((void**)&vqp,  g_vqp);

    const int DSM = 1024 + 6 * 16384;   // 99328 (6-tile ring / 3-stage pair)
    cudaFuncSetAttribute(mgemm<64, 1, 1>,  cudaFuncAttributeMaxDynamicSharedMemorySize, DSM);
    cudaFuncSetAttribute(mgemm<512, 1, 1>, cudaFuncAttributeMaxDynamicSharedMemorySize, DSM);
    cudaFuncSetAttribute(mgemm<512, 1, 0>, cudaFuncAttributeMaxDynamicSharedMemorySize, DSM);
    cudaFuncSetAttribute(mgemm<256, 0, 2>, cudaFuncAttributeMaxDynamicSharedMemorySize, DSM);
    cudaFuncSetAttribute(mgemm<512, 0, 2>, cudaFuncAttributeMaxDynamicSharedMemorySize, DSM);
    cudaFuncSetAttribute(mgemm<512, 0, 3>, cudaFuncAttributeMaxDynamicSharedMemorySize, DSM);
    cudaFuncSetAttribute(vqfused_k, cudaFuncAttributeMaxDynamicSharedMemorySize, VQ_SMEM);

    dim3 blk(256);

    // fused prep (state split + weights + codebook)
    prep_k<<<PREP_BLOCKS, blk>>>(state, ew1, ew2, ew3, dw1, dw2, dw3, cbk,
                                 spin, wsp1, wsp2, wsp3, wt1, wt2, wt3, cbh, cnp);

    // encoder: fp16 split2, tile-dedup schedule (col-fast grids)
    mgemm<64, 1, 1><<<dim3(4, RB128), blk, DSM>>>(spin, wsp1, eb1, sp1, 512, 512, nullptr, nullptr);
    mgemm<512, 1, 1><<<dim3(4, RB128), blk, DSM>>>(sp1, wsp2, eb2, sp2, 512, 512, nullptr, nullptr);
    mgemm<512, 1, 0><<<dim3(2, RB128), blk, DSM>>>(sp2, wsp3, eb3, zb, 256, 0, nullptr, nullptr);

    // fused residual VQ (codes exact fp32; q emitted as bf16)
    vqfused_k<<<RB128, blk, VQ_SMEM>>>(zb, cbh, cbk, cnp, out + 1, qbf, vqp);

    // decoder in bf16 (col-fast grids)
    mgemm<256, 0, 2><<<dim3(4, RB128), blk, DSM>>>(qbf, wt1, db1, dbA, 512, 0, nullptr, nullptr);
    mgemm<512, 0, 2><<<dim3(4, RB128), blk, DSM>>>(dbA, wt2, db2, dbB, 512, 0, nullptr, nullptr);
    mgemm<512, 0, 3><<<dim3(1, RB128), blk, DSM>>>(dbB, wt3, db3, nullptr, 56, 0, state, l1p);

    final_k<<<1, 256>>>(l1p, vqp, out);
}

// round 16
// speedup vs baseline: 1.0100x; 1.0100x over previous
#include <cuda_runtime.h>
#include <cuda_bf16.h>
#include <cuda_fp16.h>
#include <math.h>

#define NROWS 131072
#define RB128 (NROWS/128)   // 1024
#define MARGIN 1.0f
#define CAND_CAP 32

// ---------------- scratch (device globals; no allocation allowed) ----------------
__device__ float g_z   [(size_t)NROWS * 256];
__device__ __nv_bfloat16 g_qbf [(size_t)NROWS * 256];
__device__ __nv_bfloat16 g_dbA [(size_t)NROWS * 512];
__device__ __nv_bfloat16 g_dbB [(size_t)NROWS * 512];
__device__ __half g_spin[(size_t)NROWS * 128];    // state split2 fp16, Kp=64
__device__ __half g_sp1 [(size_t)NROWS * 1024];   // h1 split2, Kp=512
__device__ __half g_sp2 [(size_t)NROWS * 1024];   // h2 split2, Kp=512
__device__ __half g_wsp1[512 * 128];
__device__ __half g_wsp2[512 * 1024];
__device__ __half g_wsp3[256 * 1024];
__device__ __nv_bfloat16 g_wt1[512 * 256];
__device__ __nv_bfloat16 g_wt2[512 * 512];
__device__ __nv_bfloat16 g_wt3[56 * 512];
__device__ __nv_bfloat16 g_cbh[2 * 1024 * 256];
__device__ float g_cn  [2 * 1024];
__device__ float g_l1p [RB128];
__device__ float g_vqp [RB128];

// ---------------- helpers ----------------
__device__ __forceinline__ unsigned smaddr(const void* p) {
    return (unsigned)__cvta_generic_to_shared(p);
}
__device__ __forceinline__ void cpa16(unsigned dst, const void* src, int sz) {
    asm volatile("cp.async.cg.shared.global [%0], [%1], 16, %2;\n"
                 :: "r"(dst), "l"(src), "r"(sz));
}
#define CP_COMMIT asm volatile("cp.async.commit_group;\n")
template<int N> __device__ __forceinline__ void cp_wait() {
    asm volatile("cp.async.wait_group %0;\n" :: "n"(N));
}
__device__ __forceinline__ void mma_bf16(float* c, const unsigned* a, unsigned b0, unsigned b1) {
    asm volatile(
        "mma.sync.aligned.m16n8k16.row.col.f32.bf16.bf16.f32 "
        "{%0,%1,%2,%3}, {%4,%5,%6,%7}, {%8,%9}, {%0,%1,%2,%3};\n"
        : "+f"(c[0]), "+f"(c[1]), "+f"(c[2]), "+f"(c[3])
        : "r"(a[0]), "r"(a[1]), "r"(a[2]), "r"(a[3]), "r"(b0), "r"(b1));
}
__device__ __forceinline__ void mma_f16(float* c, const unsigned* a, unsigned b0, unsigned b1) {
    asm volatile(
        "mma.sync.aligned.m16n8k16.row.col.f32.f16.f16.f32 "
        "{%0,%1,%2,%3}, {%4,%5,%6,%7}, {%8,%9}, {%0,%1,%2,%3};\n"
        : "+f"(c[0]), "+f"(c[1]), "+f"(c[2]), "+f"(c[3])
        : "r"(a[0]), "r"(a[1]), "r"(a[2]), "r"(a[3]), "r"(b0), "r"(b1));
}
__device__ __forceinline__ void ldsm4(unsigned& r0, unsigned& r1, unsigned& r2, unsigned& r3,
                                      unsigned addr) {
    asm volatile("ldmatrix.sync.aligned.m8n8.x4.shared.b16 {%0,%1,%2,%3}, [%4];"
                 : "=r"(r0), "=r"(r1), "=r"(r2), "=r"(r3) : "r"(addr));
}
__device__ __forceinline__ unsigned fford(float f) {
    unsigned u = __float_as_uint(f);
    return (u & 0x80000000u) ? ~u : (u | 0x80000000u);
}
__device__ __forceinline__ float iford(unsigned u) {
    return __uint_as_float((u & 0x80000000u) ? (u ^ 0x80000000u) : ~u);
}
__device__ __forceinline__ void split2h(float v, __half& h0, __half& h1)
{
    h0 = __float2half_rn(v);
    float r = v - __half2float(h0);
    h1 = __float2half_rn(r);
}
#define SWZ(r, cb) ((unsigned)((r) * 128 + ((cb) ^ (((r) & 7) << 4))))

// ================= unified mma.sync GEMM engine (round-14: 3-stage, col-fast grid) =================
// MODE 0 = plain bf16, MODE 1 = fp16 split2 (3 plane pairs, pair-major).
// OUT: 0 = f32 (+bias), 1 = relu+split2 fp16 planes, 2 = relu+bf16, 3 = L1 partials.
template<int KP, int MODE, int OUT>
__global__ __launch_bounds__(256) void mgemm(
    const void* __restrict__ Av, const void* __restrict__ BTv,
    const float* __restrict__ bias, void* __restrict__ Cv, int M, int KpN,
    const float* __restrict__ Xref, float* __restrict__ part)
{
    constexpr int ROWB = (MODE == 1) ? KP * 4 : KP * 2;     // bytes per A/BT row
    constexpr int NKCB = KP / 64;                           // 128B chunks per pass
    constexpr int NCH  = (MODE == 1) ? 3 * NKCB : NKCB;
    const unsigned char* A  = (const unsigned char*)Av;
    const unsigned char* BT = (const unsigned char*)BTv;

    extern __shared__ __align__(16) char dynsm[];
    __shared__ float s_red[256];

    const int tid = threadIdx.x;
    const int lane = tid & 31, wid = tid >> 5;
    const int wm = wid & 3, wn = wid >> 2;
    const int row0 = blockIdx.y * 128;
    const int col0 = blockIdx.x * 128;

    unsigned dynb = (smaddr(dynsm) + 1023u) & ~1023u;
    unsigned Ab[3], Bb[3];
    #pragma unroll
    for (int s = 0; s < 3; s++) { Ab[s] = dynb + s * 32768u; Bb[s] = Ab[s] + 16384u; }

    float acc[2][8][4];
    #pragma unroll
    for (int a = 0; a < 2; a++)
        #pragma unroll
        for (int b = 0; b < 8; b++)
            #pragma unroll
            for (int c = 0; c < 4; c++) acc[a][b][c] = 0.f;

    auto choffB = [&](int c, int& aoffB, int& boffB) {
        if (MODE == 0) { aoffB = boffB = c * 128; }
        else {
            constexpr int PI[3] = {1, 0, 0};
            constexpr int PJ[3] = {0, 1, 0};
            int pr = c / NKCB, kc = c - pr * NKCB;
            aoffB = PI[pr] * KP * 2 + kc * 128;
            boffB = PJ[pr] * KP * 2 + kc * 128;
        }
    };
    auto fill = [&](int s, int c) {
        int aoffB, boffB; choffB(c, aoffB, boffB);
        #pragma unroll
        for (int i = 0; i < 4; i++) {
            int ch = tid + 256 * i;
            int r = ch >> 3, g = ch & 7;
            cpa16(Ab[s] + SWZ(r, g * 16),
                  A + (size_t)(row0 + r) * ROWB + aoffB + g * 16, 16);
        }
        #pragma unroll
        for (int i = 0; i < 4; i++) {
            int ch = tid + 256 * i;
            int r = ch >> 3, g = ch & 7;
            int br = col0 + r;
            int ok = (br < M);
            const unsigned char* src = BT + (size_t)(ok ? br : 0) * ROWB + boffB + g * 16;
            cpa16(Bb[s] + SWZ(r, g * 16), src, ok ? 16 : 0);
        }
    };

    const int lrow = ((lane >> 3) & 1) * 8 + (lane & 7);
    const int lcb  = (lane >= 16) ? 16 : 0;

    fill(0, 0); CP_COMMIT;
    if (NCH > 1) { fill(1, 1); CP_COMMIT; }

    for (int c = 0; c < NCH; c++) {
        const int s = c % 3;
        if (c + 1 < NCH) cp_wait<1>(); else cp_wait<0>();
        __syncthreads();
        if (c + 2 < NCH) { fill((c + 2) % 3, c + 2); CP_COMMIT; }

        const unsigned Aw = Ab[s], Bw = Bb[s];
        #pragma unroll
        for (int kki = 0; kki < 4; kki++) {
            const int kb = kki * 32;
            unsigned a[2][4];
            #pragma unroll
            for (int mf = 0; mf < 2; mf++) {
                int r = wm * 32 + mf * 16 + lrow;
                ldsm4(a[mf][0], a[mf][1], a[mf][2], a[mf][3], Aw + SWZ(r, kb + lcb));
            }
            unsigned bq[4][4];
            #pragma unroll
            for (int h = 0; h < 4; h++) {
                int r = wn * 64 + h * 16 + lrow;
                ldsm4(bq[h][0], bq[h][1], bq[h][2], bq[h][3], Bw + SWZ(r, kb + lcb));
            }
            #pragma unroll
            for (int nf = 0; nf < 8; nf++) {
                int h = nf >> 1, o = nf & 1;
                if (MODE == 1) {
                    mma_f16(acc[0][nf], a[0], bq[h][o], bq[h][o + 2]);
                    mma_f16(acc[1][nf], a[1], bq[h][o], bq[h][o + 2]);
                } else {
                    mma_bf16(acc[0][nf], a[0], bq[h][o], bq[h][o + 2]);
                    mma_bf16(acc[1][nf], a[1], bq[h][o], bq[h][o + 2]);
                }
            }
        }
    }

    const int g = lane >> 2, q2 = (lane & 3) * 2;
    if (OUT == 0) {
        float* C = (float*)Cv;
        #pragma unroll
        for (int mf = 0; mf < 2; mf++) {
            int r1 = row0 + wm * 32 + mf * 16 + g;
            #pragma unroll
            for (int nf = 0; nf < 8; nf++) {
                int cc = col0 + wn * 64 + nf * 8 + q2;
                float2 o0 = make_float2(acc[mf][nf][0] + bias[cc], acc[mf][nf][1] + bias[cc + 1]);
                float2 o1 = make_float2(acc[mf][nf][2] + bias[cc], acc[mf][nf][3] + bias[cc + 1]);
                *(float2*)(C + (size_t)r1 * M + cc) = o0;
                *(float2*)(C + (size_t)(r1 + 8) * M + cc) = o1;
            }
        }
    } else if (OUT == 1) {
        __half* C = (__half*)Cv;
        const size_t strd = 2 * (size_t)KpN;
        #pragma unroll
        for (int mf = 0; mf < 2; mf++) {
            int r1 = row0 + wm * 32 + mf * 16 + g;
            #pragma unroll
            for (int nf = 0; nf < 8; nf++) {
                int cc = col0 + wn * 64 + nf * 8 + q2;
                #pragma unroll
                for (int half = 0; half < 2; half++) {
                    int r = r1 + (half ? 8 : 0);
                    float v0 = fmaxf(acc[mf][nf][2 * half + 0] + bias[cc], 0.f);
                    float v1 = fmaxf(acc[mf][nf][2 * half + 1] + bias[cc + 1], 0.f);
                    __half a0, a1, b0, b1;
                    split2h(v0, a0, a1);
                    split2h(v1, b0, b1);
                    __half* base = C + (size_t)r * strd + cc;
                    __half2 p0; p0.x = a0; p0.y = b0;
                    __half2 p1; p1.x = a1; p1.y = b1;
                    *(__half2*)(base)       = p0;
                    *(__half2*)(base + KpN) = p1;
                }
            }
        }
    } else if (OUT == 2) {
        __nv_bfloat16* C = (__nv_bfloat16*)Cv;
        #pragma unroll
        for (int mf = 0; mf < 2; mf++) {
            int r1 = row0 + wm * 32 + mf * 16 + g;
            #pragma unroll
            for (int nf = 0; nf < 8; nf++) {
                int cc = col0 + wn * 64 + nf * 8 + q2;
                float v0 = fmaxf(acc[mf][nf][0] + bias[cc], 0.f);
                float v1 = fmaxf(acc[mf][nf][1] + bias[cc + 1], 0.f);
                float v2 = fmaxf(acc[mf][nf][2] + bias[cc], 0.f);
                float v3 = fmaxf(acc[mf][nf][3] + bias[cc + 1], 0.f);
                __nv_bfloat162 h0; h0.x = __float2bfloat16(v0); h0.y = __float2bfloat16(v1);
                __nv_bfloat162 h1; h1.x = __float2bfloat16(v2); h1.y = __float2bfloat16(v3);
                *(__nv_bfloat162*)(C + (size_t)r1 * M + cc) = h0;
                *(__nv_bfloat162*)(C + (size_t)(r1 + 8) * M + cc) = h1;
            }
        }
    } else {
        float s = 0.f;
        #pragma unroll
        for (int mf = 0; mf < 2; mf++) {
            int r1 = row0 + wm * 32 + mf * 16 + g;
            #pragma unroll
            for (int nf = 0; nf < 8; nf++) {
                int cc = col0 + wn * 64 + nf * 8 + q2;
                #pragma unroll
                for (int e = 0; e < 4; e++) {
                    int c = cc + (e & 1);
                    int r = r1 + (e >= 2 ? 8 : 0);
                    if (c < M) {
                        float v = acc[mf][nf][e] + bias[c];
                        s += fabsf(Xref[(size_t)r * M + c] - v);
                    }
                }
            }
        }
        __syncthreads();
        s_red[tid] = s;
        __syncthreads();
        #pragma unroll
        for (int off = 128; off > 0; off >>= 1) {
            if (tid < off) s_red[tid] += s_red[tid + off];
            __syncthreads();
        }
        if (tid == 0) part[blockIdx.y] = s_red[0];
    }
}

// ================= fused prep kernel (vectorized split-state & cvt sections) =================
// sections (threads): split_state 2097152 (4-wide) | cvt 131072 (4-wide) | tr1 131072 |
// tr2 262144 | tr3 28672 | sw1 32768 | sw2 262144 | sw3 131072 | cn 65536
__global__ __launch_bounds__(256) void prep_k(
    const float* __restrict__ state,
    const float* __restrict__ ew1, const float* __restrict__ ew2, const float* __restrict__ ew3,
    const float* __restrict__ dw1, const float* __restrict__ dw2, const float* __restrict__ dw3,
    const float* __restrict__ cbk,
    __half* __restrict__ spin, __half* __restrict__ wsp1, __half* __restrict__ wsp2,
    __half* __restrict__ wsp3,
    __nv_bfloat16* __restrict__ wt1, __nv_bfloat16* __restrict__ wt2,
    __nv_bfloat16* __restrict__ wt3, __nv_bfloat16* __restrict__ cbh,
    float* __restrict__ cnp)
{
    long gid = (long)blockIdx.x * 256 + threadIdx.x;

    if (gid < 2097152L) {                  // split_state 4-wide: [N][56] -> [N][2*64] fp16
        long n = gid >> 4; int grp = (int)(gid & 15);
        int k4 = grp * 4;
        float4 v = make_float4(0.f, 0.f, 0.f, 0.f);
        if (k4 < 56) v = *(const float4*)(state + n * 56 + k4);
        __half h0[4], h1[4];
        split2h(v.x, h0[0], h1[0]);
        split2h(v.y, h0[1], h1[1]);
        split2h(v.z, h0[2], h1[2]);
        split2h(v.w, h0[3], h1[3]);
        __half* d = spin + n * 128 + k4;
        __half2 p00; p00.x = h0[0]; p00.y = h0[1];
        __half2 p01; p01.x = h0[2]; p01.y = h0[3];
        __half2 p10; p10.x = h1[0]; p10.y = h1[1];
        __half2 p11; p11.x = h1[2]; p11.y = h1[3];
        *(__half2*)(d)          = p00;
        *(__half2*)(d + 2)      = p01;
        *(__half2*)(d + 64)     = p10;
        *(__half2*)(d + 66)     = p11;
        return;
    }
    gid -= 2097152L;
    if (gid < 131072) {                    // codebook fp32 -> bf16, 4-wide
        long i4 = gid * 4;
        float4 v = *(const float4*)(cbk + i4);
        __nv_bfloat162 b0; b0.x = __float2bfloat16(v.x); b0.y = __float2bfloat16(v.y);
        __nv_bfloat162 b1; b1.x = __float2bfloat16(v.z); b1.y = __float2bfloat16(v.w);
        *(__nv_bfloat162*)(cbh + i4)     = b0;
        *(__nv_bfloat162*)(cbh + i4 + 2) = b1;
        return;
    }
    gid -= 131072;
    if (gid < 131072) {
        int k = (int)(gid / 512), m = (int)(gid % 512);
        wt1[(size_t)m * 256 + k] = __float2bfloat16(dw1[gid]);
        return;
    }
    gid -= 131072;
    if (gid < 262144) {
        int k = (int)(gid / 512), m = (int)(gid % 512);
        wt2[(size_t)m * 512 + k] = __float2bfloat16(dw2[gid]);
        return;
    }
    gid -= 262144;
    if (gid < 28672) {
        int k = (int)(gid / 56), m = (int)(gid % 56);
        wt3[(size_t)m * 512 + k] = __float2bfloat16(dw3[gid]);
        return;
    }
    gid -= 28672;
    if (gid < 32768) {
        int m = (int)(gid / 64), k = (int)(gid % 64);
        float v = (k < 56) ? ew1[(size_t)k * 512 + m] : 0.f;
        __half h0, h1; split2h(v, h0, h1);
        __half* d = wsp1 + (size_t)m * 128;
        d[k] = h0; d[64 + k] = h1;
        return;
    }
    gid -= 32768;
    if (gid < 262144) {
        int m = (int)(gid / 512), k = (int)(gid % 512);
        float v = ew2[(size_t)k * 512 + m];
        __half h0, h1; split2h(v, h0, h1);
        __half* d = wsp2 + (size_t)m * 1024;
        d[k] = h0; d[512 + k] = h1;
        return;
    }
    gid -= 262144;
    if (gid < 131072) {
        int m = (int)(gid / 512), k = (int)(gid % 512);
        float v = ew3[(size_t)k * 256 + m];
        __half h0, h1; split2h(v, h0, h1);
        __half* d = wsp3 + (size_t)m * 1024;
        d[k] = h0; d[512 + k] = h1;
        return;
    }
    gid -= 131072;
    if (gid < 65536) {
        int w = (int)(gid >> 5);
        int lane = (int)(gid & 31);
        const float* c = cbk + (size_t)w * 256;
        float s = 0.f;
        #pragma unroll
        for (int k = lane; k < 256; k += 32) s = fmaf(c[k], c[k], s);
        #pragma unroll
        for (int off = 16; off > 0; off >>= 1) s += __shfl_xor_sync(0xffffffff, s, off);
        if (lane == 0) cnp[w] = 0.5f * s;
    }
}
#define PREP_THREADS (2097152L + 131072 + 131072 + 262144 + 28672 + 32768 + 262144 + 131072 + 65536)
#define PREP_BLOCKS  ((int)((PREP_THREADS + 255) / 256))

// ================= fused residual-VQ (unchanged) =================
#define VQ_SMEM (216068 + 1024)

__device__ __forceinline__ void vq_score8(
    unsigned AsB, unsigned BsB, char* smc,
    const __nv_bfloat16* __restrict__ cbh, const float* __restrict__ cn,
    int* cand, unsigned* rowmin, int* cnt,
    int tid, int lane, int wid, int wm, int wn, int g, int q2, int lrow, int lcb)
{
    #pragma unroll
    for (int i = 0; i < 16; i++) {
        int ch = tid + 256 * i;
        int r = ch >> 5, gg = ch & 31;
        cpa16(BsB + (unsigned)(gg >> 3) * 16384u + SWZ(r, (gg & 7) * 16),
              cbh + (size_t)r * 256 + gg * 8, 16);
    }
    CP_COMMIT;

    for (int t = 0; t < 8; t++) {
        if (t < 7) {
            unsigned stb = BsB + (unsigned)((t + 1) & 1) * 65536u;
            #pragma unroll
            for (int i = 0; i < 16; i++) {
                int ch = tid + 256 * i;
                int r = ch >> 5, gg = ch & 31;
                cpa16(stb + (unsigned)(gg >> 3) * 16384u + SWZ(r, (gg & 7) * 16),
                      cbh + (size_t)((t + 1) * 128 + r) * 256 + gg * 8, 16);
            }
            CP_COMMIT;
            cp_wait<1>();
        } else {
            cp_wait<0>();
        }
        __syncthreads();

        float acc[2][8][4];
        #pragma unroll
        for (int a = 0; a < 2; a++)
            #pragma unroll
            for (int b = 0; b < 8; b++)
                #pragma unroll
                for (int c = 0; c < 4; c++) acc[a][b][c] = 0.f;

        const unsigned Bst = BsB + (unsigned)(t & 1) * 65536u;
        #pragma unroll
        for (int kk = 0; kk < 256; kk += 16) {
            int kb = kk >> 6;
            int kloc = (kk & 63) * 2;
            unsigned a[2][4];
            #pragma unroll
            for (int mf = 0; mf < 2; mf++) {
                int r = wm * 32 + mf * 16 + lrow;
                ldsm4(a[mf][0], a[mf][1], a[mf][2], a[mf][3],
                      AsB + (unsigned)kb * 16384u + SWZ(r, kloc + lcb));
            }
            unsigned bq[4][4];
            #pragma unroll
            for (int h = 0; h < 4; h++) {
                int r = wn * 64 + h * 16 + lrow;
                ldsm4(bq[h][0], bq[h][1], bq[h][2], bq[h][3],
                      Bst + (unsigned)kb * 16384u + SWZ(r, kloc + lcb));
            }
            #pragma unroll
            for (int nf = 0; nf < 8; nf++) {
                int h = nf >> 1, o = nf & 1;
                mma_bf16(acc[0][nf], a[0], bq[h][o], bq[h][o + 2]);
                mma_bf16(acc[1][nf], a[1], bq[h][o], bq[h][o + 2]);
            }
        }

        #pragma unroll
        for (int mf = 0; mf < 2; mf++) {
            int r1 = wm * 32 + mf * 16 + g;
            float m1 = 1e30f, m2 = 1e30f;
            #pragma unroll
            for (int nf = 0; nf < 8; nf++) {
                int cl = wn * 64 + nf * 8 + q2;
                float cn0 = __ldg(cn + t * 128 + cl);
                float cn1 = __ldg(cn + t * 128 + cl + 1);
                float s0 = cn0 - acc[mf][nf][0];
                float s1 = cn1 - acc[mf][nf][1];
                float s2 = cn0 - acc[mf][nf][2];
                float s3 = cn1 - acc[mf][nf][3];
                acc[mf][nf][0] = s0; acc[mf][nf][1] = s1;
                acc[mf][nf][2] = s2; acc[mf][nf][3] = s3;
                m1 = fminf(m1, fminf(s0, s1));
                m2 = fminf(m2, fminf(s2, s3));
            }
            atomicMin(&rowmin[r1], fford(m1));
            atomicMin(&rowmin[r1 + 8], fford(m2));
        }
        __syncthreads();
        #pragma unroll
        for (int mf = 0; mf < 2; mf++) {
            int r1 = wm * 32 + mf * 16 + g;
            float thr1 = iford(rowmin[r1]) + MARGIN;
            float thr2 = iford(rowmin[r1 + 8]) + MARGIN;
            #pragma unroll
            for (int nf = 0; nf < 8; nf++) {
                int code = t * 128 + wn * 64 + nf * 8 + q2;
                #pragma unroll
                for (int e = 0; e < 4; e++) {
                    float s = acc[mf][nf][e];
                    int r = (e >= 2) ? (r1 + 8) : r1;
                    float thr = (e >= 2) ? thr2 : thr1;
                    if (s <= thr) {
                        int p = atomicAdd(&cnt[r], 1);
                        if (p < CAND_CAP) cand[r * CAND_CAP + p] = code + (e & 1);
                    }
                }
            }
        }
        __syncthreads();
    }
}

__device__ __forceinline__ void vq_rescue(
    const float rr[8], const float* __restrict__ cbf, const float* __restrict__ cn,
    const int* cand, int row, int cv, int lane, int& bc_out)
{
    float bv = 1e30f; int bc = 0;
    if (cv <= CAND_CAP) {
        for (int i = 0; i < cv; i++) {
            int c = cand[row * CAND_CAP + i];
            const float* cp = cbf + (size_t)c * 256 + lane * 8;
            float d = 0.f;
            #pragma unroll
            for (int e = 0; e < 8; e++) d = fmaf(rr[e], __ldg(cp + e), d);
            #pragma unroll
            for (int off = 16; off > 0; off >>= 1) d += __shfl_xor_sync(0xffffffff, d, off);
            float s = __ldg(cn + c) - d;
            if (s < bv || (s == bv && c < bc)) { bv = s; bc = c; }
        }
    } else {
        for (int c = 0; c < 1024; c++) {
            const float* cp = cbf + (size_t)c * 256 + lane * 8;
            float d = 0.f;
            #pragma unroll
            for (int e = 0; e < 8; e++) d = fmaf(rr[e], __ldg(cp + e), d);
            #pragma unroll
            for (int off = 16; off > 0; off >>= 1) d += __shfl_xor_sync(0xffffffff, d, off);
            float s = __ldg(cn + c) - d;
            if (s < bv || (s == bv && c < bc)) { bv = s; bc = c; }
        }
    }
    bc_out = bc;
}

__global__ __launch_bounds__(256) void vqfused_k(
    const float* __restrict__ zg, const __nv_bfloat16* __restrict__ cbh,
    const float* __restrict__ cbf, const float* __restrict__ cn,
    float* __restrict__ codes_out, __nv_bfloat16* __restrict__ qbf,
    float* __restrict__ vqpart)
{
    extern __shared__ __align__(16) char sm[];
    unsigned dynb = (smaddr(sm) + 1023u) & ~1023u;
    char* smc = sm + (int)(dynb - smaddr(sm));
    const unsigned AsB = dynb;
    const unsigned BsB = dynb + 65536u;
    int*      cand   = (int*)     (smc + 196608);
    unsigned* rowmin = (unsigned*)(smc + 212992);
    int*      cnt    = (int*)     (smc + 213504);
    int*      ch0    = (int*)     (smc + 214016);
    int*      ch1    = (int*)     (smc + 214528);
    float*    red    = (float*)   (smc + 215040);
    float*    s0p    = (float*)   (smc + 216064);

    const int tid = threadIdx.x;
    const int lane = tid & 31, wid = tid >> 5;
    const int wm = wid & 3, wn = wid >> 2;
    const size_t row0 = (size_t)blockIdx.x * 128;
    const int g = lane >> 2, q2 = (lane & 3) * 2;
    const int lrow = ((lane >> 3) & 1) * 8 + (lane & 7);
    const int lcb  = (lane >= 16) ? 16 : 0;

    const __nv_bfloat16* cbh1 = cbh + 1024 * 256;
    const float* cbf1 = cbf + 1024 * 256;
    const float* cn1  = cn + 1024;

    if (tid < 128) { rowmin[tid] = 0xFFFFFFFFu; cnt[tid] = 0; }

    #pragma unroll
    for (int i = 0; i < 32; i++) {
        int e = tid + 256 * i;
        int r = e >> 6, c4 = e & 63;
        float4 v = *(const float4*)(zg + (row0 + r) * 256 + 4 * c4);
        __nv_bfloat162 h0; h0.x = __float2bfloat16(v.x); h0.y = __float2bfloat16(v.y);
        __nv_bfloat162 h1; h1.x = __float2bfloat16(v.z); h1.y = __float2bfloat16(v.w);
        uint2 p; p.x = *(unsigned*)&h0; p.y = *(unsigned*)&h1;
        int kb = c4 >> 4;
        unsigned off = (unsigned)kb * 16384u + (unsigned)r * 128u
                     + (((unsigned)((c4 * 8) & 127)) ^ (((unsigned)r & 7u) << 4));
        *(uint2*)(smc + off) = p;
    }
    __syncthreads();

    vq_score8(AsB, BsB, smc, cbh, cn, cand, rowmin, cnt,
              tid, lane, wid, wm, wn, g, q2, lrow, lcb);

    for (int j = 0; j < 16; j++) {
        int row = wid + 8 * j;
        const float* rp = zg + (row0 + row) * 256 + lane * 8;
        float4 u = *(const float4*)rp;
        float4 v = *(const float4*)(rp + 4);
        float rr[8] = {u.x, u.y, u.z, u.w, v.x, v.y, v.z, v.w};
        int bc;
        vq_rescue(rr, cbf, cn, cand, row, cnt[row], lane, bc);
        if (lane == 0) {
            ch0[row] = bc;
            codes_out[(row0 + row) * 2 + 0] = (float)bc;
        }
    }
    __syncthreads();

    float vac = 0.f;
    #pragma unroll
    for (int i = 0; i < 32; i++) {
        int e = tid + 256 * i;
        int r = e >> 6, c4 = e & 63;
        int c = ch0[r];
        size_t off = (row0 + r) * 256 + 4 * c4;
        float4 cvv = *(const float4*)(cbf + (size_t)c * 256 + 4 * c4);
        float4 zv  = *(const float4*)(zg + off);
        float4 dv = make_float4(zv.x - cvv.x, zv.y - cvv.y, zv.z - cvv.z, zv.w - cvv.w);
        vac += dv.x * dv.x + dv.y * dv.y + dv.z * dv.z + dv.w * dv.w;
        __nv_bfloat162 h0; h0.x = __float2bfloat16(dv.x); h0.y = __float2bfloat16(dv.y);
        __nv_bfloat162 h1; h1.x = __float2bfloat16(dv.z); h1.y = __float2bfloat16(dv.w);
        uint2 p; p.x = *(unsigned*)&h0; p.y = *(unsigned*)&h1;
        int kb = c4 >> 4;
        unsigned soff = (unsigned)kb * 16384u + (unsigned)r * 128u
                      + (((unsigned)((c4 * 8) & 127)) ^ (((unsigned)r & 7u) << 4));
        *(uint2*)(smc + soff) = p;
    }
    red[tid] = vac;
    __syncthreads();
    #pragma unroll
    for (int off = 128; off > 0; off >>= 1) {
        if (tid < off) red[tid] += red[tid + off];
        __syncthreads();
    }
    if (tid == 0) *s0p = red[0];
    if (tid < 128) { rowmin[tid] = 0xFFFFFFFFu; cnt[tid] = 0; }
    __syncthreads();

    vq_score8(AsB, BsB, smc, cbh1, cn1, cand, rowmin, cnt,
              tid, lane, wid, wm, wn, g, q2, lrow, lcb);

    for (int j = 0; j < 16; j++) {
        int row = wid + 8 * j;
        const float* rp = zg + (row0 + row) * 256 + lane * 8;
        const float* cp0 = cbf + (size_t)ch0[row] * 256 + lane * 8;
        float4 u = *(const float4*)rp;
        float4 v = *(const float4*)(rp + 4);
        float4 a = *(const float4*)cp0;
        float4 b = *(const float4*)(cp0 + 4);
        float rr[8] = {u.x - a.x, u.y - a.y, u.z - a.z, u.w - a.w,
                       v.x - b.x, v.y - b.y, v.z - b.z, v.w - b.w};
        int bc;
        vq_rescue(rr, cbf1, cn1, cand, row, cnt[row], lane, bc);
        if (lane == 0) {
            ch1[row] = bc;
            codes_out[(row0 + row) * 2 + 1] = (float)bc;
        }
    }
    __syncthreads();

    vac = 0.f;
    #pragma unroll
    for (int i = 0; i < 32; i++) {
        int e = tid + 256 * i;
        int r = e >> 6, c4 = e & 63;
        int c = ch1[r], c0 = ch0[r];
        size_t off = (row0 + r) * 256 + 4 * c4;
        float4 cvv = *(const float4*)(cbf1 + (size_t)c * 256 + 4 * c4);
        float4 q0v = *(const float4*)(cbf + (size_t)c0 * 256 + 4 * c4);
        float4 zv  = *(const float4*)(zg + off);
        float4 rv = make_float4(zv.x - q0v.x, zv.y - q0v.y, zv.z - q0v.z, zv.w - q0v.w);
        float4 dv = make_float4(rv.x - cvv.x, rv.y - cvv.y, rv.z - cvv.z, rv.w - cvv.w);
        vac += dv.x * dv.x + dv.y * dv.y + dv.z * dv.z + dv.w * dv.w;
        float4 sv = make_float4(q0v.x + cvv.x, q0v.y + cvv.y, q0v.z + cvv.z, q0v.w + cvv.w);
        __nv_bfloat162 h0; h0.x = __float2bfloat16(sv.x); h0.y = __float2bfloat16(sv.y);
        __nv_bfloat162 h1; h1.x = __float2bfloat16(sv.z); h1.y = __float2bfloat16(sv.w);
        *(__nv_bfloat162*)(qbf + off) = h0;
        *(__nv_bfloat162*)(qbf + off + 2) = h1;
    }
    red[tid] = vac;
    __syncthreads();
    #pragma unroll
    for (int off = 128; off > 0; off >>= 1) {
        if (tid < off) red[tid] += red[tid + off];
        __syncthreads();
    }
    if (tid == 0) vqpart[blockIdx.x] = *s0p + red[0];
}

// ================= final deterministic loss combine =================
__global__ __launch_bounds__(256) void final_k(
    const float* __restrict__ l1p, const float* __restrict__ vqp, float* __restrict__ out)
{
    __shared__ float sa[256], sb[256];
    float a = 0.f, b = 0.f;
    for (int i = threadIdx.x; i < RB128; i += 256) { a += l1p[i]; b += vqp[i]; }
    sa[threadIdx.x] = a; sb[threadIdx.x] = b;
    __syncthreads();
    #pragma unroll
    for (int off = 128; off > 0; off >>= 1) {
        if (threadIdx.x < off) {
            sa[threadIdx.x] += sa[threadIdx.x + off];
            sb[threadIdx.x] += sb[threadIdx.x + off];
        }
        __syncthreads();
    }
    if (threadIdx.x == 0) {
        float enc_loss = sa[0] / (131072.0f * 56.0f);
        float vq_loss  = sb[0] / (131072.0f * 256.0f);
        out[0] = enc_loss + 5.0f * vq_loss;
    }
}

// ================= launch =================
extern "C" void kernel_launch(void* const* d_in, const int* in_sizes, int n_in,
                              void* d_out, int out_size)
{
    const float* state = (const float*)d_in[0];
    const float* ew1 = (const float*)d_in[1];
    const float* eb1 = (const float*)d_in[2];
    const float* ew2 = (const float*)d_in[3];
    const float* eb2 = (const float*)d_in[4];
    const float* ew3 = (const float*)d_in[5];
    const float* eb3 = (const float*)d_in[6];
    const float* dw1 = (const float*)d_in[7];
    const float* db1 = (const float*)d_in[8];
    const float* dw2 = (const float*)d_in[9];
    const float* db2 = (const float*)d_in[10];
    const float* dw3 = (const float*)d_in[11];
    const float* db3 = (const float*)d_in[12];
    const float* cbk = (const float*)d_in[13];
    float* out = (float*)d_out;

    float *zb, *cnp, *l1p, *vqp;
    __nv_bfloat16 *qbf, *dbA, *dbB, *cbh, *wt1, *wt2, *wt3;
    __half *spin, *sp1, *sp2, *wsp1, *wsp2, *wsp3;
    cudaGetSymbolAddress((void**)&zb,   g_z);
    cudaGetSymbolAddress((void**)&qbf,  g_qbf);
    cudaGetSymbolAddress((void**)&dbA,  g_dbA);
    cudaGetSymbolAddress((void**)&dbB,  g_dbB);
    cudaGetSymbolAddress((void**)&spin, g_spin);
    cudaGetSymbolAddress((void**)&sp1,  g_sp1);
    cudaGetSymbolAddress((void**)&sp2,  g_sp2);
    cudaGetSymbolAddress((void**)&wsp1, g_wsp1);
    cudaGetSymbolAddress((void**)&wsp2, g_wsp2);
    cudaGetSymbolAddress((void**)&wsp3, g_wsp3);
    cudaGetSymbolAddress((void**)&wt1,  g_wt1);
    cudaGetSymbolAddress((void**)&wt2,  g_wt2);
    cudaGetSymbolAddress((void**)&wt3,  g_wt3);
    cudaGetSymbolAddress((void**)&cbh,  g_cbh);
    cudaGetSymbolAddress((void**)&cnp,  g_cn);
    cudaGetSymbolAddress((void**)&l1p,  g_l1p);
    cudaGetSymbolAddress((void**)&vqp,  g_vqp);

    const int DSM = 1024 + 3 * 32768;   // 99328
    cudaFuncSetAttribute(mgemm<64, 1, 1>,  cudaFuncAttributeMaxDynamicSharedMemorySize, DSM);
    cudaFuncSetAttribute(mgemm<512, 1, 1>, cudaFuncAttributeMaxDynamicSharedMemorySize, DSM);
    cudaFuncSetAttribute(mgemm<512, 1, 0>, cudaFuncAttributeMaxDynamicSharedMemorySize, DSM);
    cudaFuncSetAttribute(mgemm<256, 0, 2>, cudaFuncAttributeMaxDynamicSharedMemorySize, DSM);
    cudaFuncSetAttribute(mgemm<512, 0, 2>, cudaFuncAttributeMaxDynamicSharedMemorySize, DSM);
    cudaFuncSetAttribute(mgemm<512, 0, 3>, cudaFuncAttributeMaxDynamicSharedMemorySize, DSM);
    cudaFuncSetAttribute(vqfused_k, cudaFuncAttributeMaxDynamicSharedMemorySize, VQ_SMEM);

    dim3 blk(256);

    // fused prep (state split + weights + codebook; vectorized big sections)
    prep_k<<<PREP_BLOCKS, blk>>>(state, ew1, ew2, ew3, dw1, dw2, dw3, cbk,
                                 spin, wsp1, wsp2, wsp3, wt1, wt2, wt3, cbh, cnp);

    // encoder: fp16 split2 (round-14 engine, col-fast grids)
    mgemm<64, 1, 1><<<dim3(4, RB128), blk, DSM>>>(spin, wsp1, eb1, sp1, 512, 512, nullptr, nullptr);
    mgemm<512, 1, 1><<<dim3(4, RB128), blk, DSM>>>(sp1, wsp2, eb2, sp2, 512, 512, nullptr, nullptr);
    mgemm<512, 1, 0><<<dim3(2, RB128), blk, DSM>>>(sp2, wsp3, eb3, zb, 256, 0, nullptr, nullptr);

    // fused residual VQ (codes exact fp32; q emitted as bf16)
    vqfused_k<<<RB128, blk, VQ_SMEM>>>(zb, cbh, cbk, cnp, out + 1, qbf, vqp);

    // decoder in bf16 (col-fast grids)
    mgemm<256, 0, 2><<<dim3(4, RB128), blk, DSM>>>(qbf, wt1, db1, dbA, 512, 0, nullptr, nullptr);
    mgemm<512, 0, 2><<<dim3(4, RB128), blk, DSM>>>(dbA, wt2, db2, dbB, 512, 0, nullptr, nullptr);
    mgemm<512, 0, 3><<<dim3(1, RB128), blk, DSM>>>(dbB, wt3, db3, nullptr, 56, 0, state, l1p);

    final_k<<<1, 256>>>(l1p, vqp, out);
}

// round 17
// speedup vs baseline: 1.0628x; 1.0523x over previous
#include <cuda_runtime.h>
#include <cuda_bf16.h>
#include <cuda_fp16.h>
#include <math.h>

#define NROWS 131072
#define RB128 (NROWS/128)   // 1024
#define MARGIN 1.0f
#define CAND_CAP 32

// ---------------- scratch (device globals; no allocation allowed) ----------------
__device__ float g_z   [(size_t)NROWS * 256];
__device__ __nv_bfloat16 g_qbf [(size_t)NROWS * 256];
__device__ __nv_bfloat16 g_dbA [(size_t)NROWS * 512];
__device__ __nv_bfloat16 g_dbB [(size_t)NROWS * 512];
__device__ __half g_spin[(size_t)NROWS * 128];    // state split2 fp16, Kp=64
__device__ __half g_sp1 [(size_t)NROWS * 1024];   // h1 split2, Kp=512
__device__ __half g_sp2 [(size_t)NROWS * 1024];   // h2 split2, Kp=512
__device__ __half g_wsp1[512 * 128];
__device__ __half g_wsp2[512 * 1024];
__device__ __half g_wsp3[256 * 1024];
__device__ __nv_bfloat16 g_wt1[512 * 256];
__device__ __nv_bfloat16 g_wt2[512 * 512];
__device__ __nv_bfloat16 g_wt3[56 * 512];
__device__ __nv_bfloat16 g_cbh[2 * 1024 * 256];
__device__ float g_cn  [2 * 1024];
__device__ float g_l1p [RB128];
__device__ float g_vqp [RB128];

// ---------------- helpers ----------------
__device__ __forceinline__ unsigned smaddr(const void* p) {
    return (unsigned)__cvta_generic_to_shared(p);
}
__device__ __forceinline__ void cpa16(unsigned dst, const void* src, int sz) {
    asm volatile("cp.async.cg.shared.global [%0], [%1], 16, %2;\n"
                 :: "r"(dst), "l"(src), "r"(sz));
}
#define CP_COMMIT asm volatile("cp.async.commit_group;\n")
template<int N> __device__ __forceinline__ void cp_wait() {
    asm volatile("cp.async.wait_group %0;\n" :: "n"(N));
}
__device__ __forceinline__ void mma_bf16(float* c, const unsigned* a, unsigned b0, unsigned b1) {
    asm volatile(
        "mma.sync.aligned.m16n8k16.row.col.f32.bf16.bf16.f32 "
        "{%0,%1,%2,%3}, {%4,%5,%6,%7}, {%8,%9}, {%0,%1,%2,%3};\n"
        : "+f"(c[0]), "+f"(c[1]), "+f"(c[2]), "+f"(c[3])
        : "r"(a[0]), "r"(a[1]), "r"(a[2]), "r"(a[3]), "r"(b0), "r"(b1));
}
__device__ __forceinline__ void mma_f16(float* c, const unsigned* a, unsigned b0, unsigned b1) {
    asm volatile(
        "mma.sync.aligned.m16n8k16.row.col.f32.f16.f16.f32 "
        "{%0,%1,%2,%3}, {%4,%5,%6,%7}, {%8,%9}, {%0,%1,%2,%3};\n"
        : "+f"(c[0]), "+f"(c[1]), "+f"(c[2]), "+f"(c[3])
        : "r"(a[0]), "r"(a[1]), "r"(a[2]), "r"(a[3]), "r"(b0), "r"(b1));
}
__device__ __forceinline__ void ldsm4(unsigned& r0, unsigned& r1, unsigned& r2, unsigned& r3,
                                      unsigned addr) {
    asm volatile("ldmatrix.sync.aligned.m8n8.x4.shared.b16 {%0,%1,%2,%3}, [%4];"
                 : "=r"(r0), "=r"(r1), "=r"(r2), "=r"(r3) : "r"(addr));
}
__device__ __forceinline__ unsigned fford(float f) {
    unsigned u = __float_as_uint(f);
    return (u & 0x80000000u) ? ~u : (u | 0x80000000u);
}
__device__ __forceinline__ float iford(unsigned u) {
    return __uint_as_float((u & 0x80000000u) ? (u ^ 0x80000000u) : ~u);
}
__device__ __forceinline__ void split2h(float v, __half& h0, __half& h1)
{
    h0 = __float2half_rn(v);
    float r = v - __half2float(h0);
    h1 = __float2half_rn(r);
}
#define SWZ(r, cb) ((unsigned)((r) * 128 + ((cb) ^ (((r) & 7) << 4))))

// ================= unified mma.sync GEMM engine (round-14 form, unchanged) =================
template<int KP, int MODE, int OUT>
__global__ __launch_bounds__(256) void mgemm(
    const void* __restrict__ Av, const void* __restrict__ BTv,
    const float* __restrict__ bias, void* __restrict__ Cv, int M, int KpN,
    const float* __restrict__ Xref, float* __restrict__ part)
{
    constexpr int ROWB = (MODE == 1) ? KP * 4 : KP * 2;
    constexpr int NKCB = KP / 64;
    constexpr int NCH  = (MODE == 1) ? 3 * NKCB : NKCB;
    const unsigned char* A  = (const unsigned char*)Av;
    const unsigned char* BT = (const unsigned char*)BTv;

    extern __shared__ __align__(16) char dynsm[];
    __shared__ float s_red[256];

    const int tid = threadIdx.x;
    const int lane = tid & 31, wid = tid >> 5;
    const int wm = wid & 3, wn = wid >> 2;
    const int row0 = blockIdx.y * 128;
    const int col0 = blockIdx.x * 128;

    unsigned dynb = (smaddr(dynsm) + 1023u) & ~1023u;
    unsigned Ab[3], Bb[3];
    #pragma unroll
    for (int s = 0; s < 3; s++) { Ab[s] = dynb + s * 32768u; Bb[s] = Ab[s] + 16384u; }

    float acc[2][8][4];
    #pragma unroll
    for (int a = 0; a < 2; a++)
        #pragma unroll
        for (int b = 0; b < 8; b++)
            #pragma unroll
            for (int c = 0; c < 4; c++) acc[a][b][c] = 0.f;

    auto choffB = [&](int c, int& aoffB, int& boffB) {
        if (MODE == 0) { aoffB = boffB = c * 128; }
        else {
            constexpr int PI[3] = {1, 0, 0};
            constexpr int PJ[3] = {0, 1, 0};
            int pr = c / NKCB, kc = c - pr * NKCB;
            aoffB = PI[pr] * KP * 2 + kc * 128;
            boffB = PJ[pr] * KP * 2 + kc * 128;
        }
    };
    auto fill = [&](int s, int c) {
        int aoffB, boffB; choffB(c, aoffB, boffB);
        #pragma unroll
        for (int i = 0; i < 4; i++) {
            int ch = tid + 256 * i;
            int r = ch >> 3, g = ch & 7;
            cpa16(Ab[s] + SWZ(r, g * 16),
                  A + (size_t)(row0 + r) * ROWB + aoffB + g * 16, 16);
        }
        #pragma unroll
        for (int i = 0; i < 4; i++) {
            int ch = tid + 256 * i;
            int r = ch >> 3, g = ch & 7;
            int br = col0 + r;
            int ok = (br < M);
            const unsigned char* src = BT + (size_t)(ok ? br : 0) * ROWB + boffB + g * 16;
            cpa16(Bb[s] + SWZ(r, g * 16), src, ok ? 16 : 0);
        }
    };

    const int lrow = ((lane >> 3) & 1) * 8 + (lane & 7);
    const int lcb  = (lane >= 16) ? 16 : 0;

    fill(0, 0); CP_COMMIT;
    if (NCH > 1) { fill(1, 1); CP_COMMIT; }

    for (int c = 0; c < NCH; c++) {
        const int s = c % 3;
        if (c + 1 < NCH) cp_wait<1>(); else cp_wait<0>();
        __syncthreads();
        if (c + 2 < NCH) { fill((c + 2) % 3, c + 2); CP_COMMIT; }

        const unsigned Aw = Ab[s], Bw = Bb[s];
        #pragma unroll
        for (int kki = 0; kki < 4; kki++) {
            const int kb = kki * 32;
            unsigned a[2][4];
            #pragma unroll
            for (int mf = 0; mf < 2; mf++) {
                int r = wm * 32 + mf * 16 + lrow;
                ldsm4(a[mf][0], a[mf][1], a[mf][2], a[mf][3], Aw + SWZ(r, kb + lcb));
            }
            unsigned bq[4][4];
            #pragma unroll
            for (int h = 0; h < 4; h++) {
                int r = wn * 64 + h * 16 + lrow;
                ldsm4(bq[h][0], bq[h][1], bq[h][2], bq[h][3], Bw + SWZ(r, kb + lcb));
            }
            #pragma unroll
            for (int nf = 0; nf < 8; nf++) {
                int h = nf >> 1, o = nf & 1;
                if (MODE == 1) {
                    mma_f16(acc[0][nf], a[0], bq[h][o], bq[h][o + 2]);
                    mma_f16(acc[1][nf], a[1], bq[h][o], bq[h][o + 2]);
                } else {
                    mma_bf16(acc[0][nf], a[0], bq[h][o], bq[h][o + 2]);
                    mma_bf16(acc[1][nf], a[1], bq[h][o], bq[h][o + 2]);
                }
            }
        }
    }

    const int g = lane >> 2, q2 = (lane & 3) * 2;
    if (OUT == 0) {
        float* C = (float*)Cv;
        #pragma unroll
        for (int mf = 0; mf < 2; mf++) {
            int r1 = row0 + wm * 32 + mf * 16 + g;
            #pragma unroll
            for (int nf = 0; nf < 8; nf++) {
                int cc = col0 + wn * 64 + nf * 8 + q2;
                float2 o0 = make_float2(acc[mf][nf][0] + bias[cc], acc[mf][nf][1] + bias[cc + 1]);
                float2 o1 = make_float2(acc[mf][nf][2] + bias[cc], acc[mf][nf][3] + bias[cc + 1]);
                *(float2*)(C + (size_t)r1 * M + cc) = o0;
                *(float2*)(C + (size_t)(r1 + 8) * M + cc) = o1;
            }
        }
    } else if (OUT == 1) {
        __half* C = (__half*)Cv;
        const size_t strd = 2 * (size_t)KpN;
        #pragma unroll
        for (int mf = 0; mf < 2; mf++) {
            int r1 = row0 + wm * 32 + mf * 16 + g;
            #pragma unroll
            for (int nf = 0; nf < 8; nf++) {
                int cc = col0 + wn * 64 + nf * 8 + q2;
                #pragma unroll
                for (int half = 0; half < 2; half++) {
                    int r = r1 + (half ? 8 : 0);
                    float v0 = fmaxf(acc[mf][nf][2 * half + 0] + bias[cc], 0.f);
                    float v1 = fmaxf(acc[mf][nf][2 * half + 1] + bias[cc + 1], 0.f);
                    __half a0, a1, b0, b1;
                    split2h(v0, a0, a1);
                    split2h(v1, b0, b1);
                    __half* base = C + (size_t)r * strd + cc;
                    __half2 p0; p0.x = a0; p0.y = b0;
                    __half2 p1; p1.x = a1; p1.y = b1;
                    *(__half2*)(base)       = p0;
                    *(__half2*)(base + KpN) = p1;
                }
            }
        }
    } else if (OUT == 2) {
        __nv_bfloat16* C = (__nv_bfloat16*)Cv;
        #pragma unroll
        for (int mf = 0; mf < 2; mf++) {
            int r1 = row0 + wm * 32 + mf * 16 + g;
            #pragma unroll
            for (int nf = 0; nf < 8; nf++) {
                int cc = col0 + wn * 64 + nf * 8 + q2;
                float v0 = fmaxf(acc[mf][nf][0] + bias[cc], 0.f);
                float v1 = fmaxf(acc[mf][nf][1] + bias[cc + 1], 0.f);
                float v2 = fmaxf(acc[mf][nf][2] + bias[cc], 0.f);
                float v3 = fmaxf(acc[mf][nf][3] + bias[cc + 1], 0.f);
                __nv_bfloat162 h0; h0.x = __float2bfloat16(v0); h0.y = __float2bfloat16(v1);
                __nv_bfloat162 h1; h1.x = __float2bfloat16(v2); h1.y = __float2bfloat16(v3);
                *(__nv_bfloat162*)(C + (size_t)r1 * M + cc) = h0;
                *(__nv_bfloat162*)(C + (size_t)(r1 + 8) * M + cc) = h1;
            }
        }
    } else {
        float s = 0.f;
        #pragma unroll
        for (int mf = 0; mf < 2; mf++) {
            int r1 = row0 + wm * 32 + mf * 16 + g;
            #pragma unroll
            for (int nf = 0; nf < 8; nf++) {
                int cc = col0 + wn * 64 + nf * 8 + q2;
                #pragma unroll
                for (int e = 0; e < 4; e++) {
                    int c = cc + (e & 1);
                    int r = r1 + (e >= 2 ? 8 : 0);
                    if (c < M) {
                        float v = acc[mf][nf][e] + bias[c];
                        s += fabsf(Xref[(size_t)r * M + c] - v);
                    }
                }
            }
        }
        __syncthreads();
        s_red[tid] = s;
        __syncthreads();
        #pragma unroll
        for (int off = 128; off > 0; off >>= 1) {
            if (tid < off) s_red[tid] += s_red[tid + off];
            __syncthreads();
        }
        if (tid == 0) part[blockIdx.y] = s_red[0];
    }
}

// ================= fused prep kernel (round-16 vectorized form, unchanged) =================
__global__ __launch_bounds__(256) void prep_k(
    const float* __restrict__ state,
    const float* __restrict__ ew1, const float* __restrict__ ew2, const float* __restrict__ ew3,
    const float* __restrict__ dw1, const float* __restrict__ dw2, const float* __restrict__ dw3,
    const float* __restrict__ cbk,
    __half* __restrict__ spin, __half* __restrict__ wsp1, __half* __restrict__ wsp2,
    __half* __restrict__ wsp3,
    __nv_bfloat16* __restrict__ wt1, __nv_bfloat16* __restrict__ wt2,
    __nv_bfloat16* __restrict__ wt3, __nv_bfloat16* __restrict__ cbh,
    float* __restrict__ cnp)
{
    long gid = (long)blockIdx.x * 256 + threadIdx.x;

    if (gid < 2097152L) {
        long n = gid >> 4; int grp = (int)(gid & 15);
        int k4 = grp * 4;
        float4 v = make_float4(0.f, 0.f, 0.f, 0.f);
        if (k4 < 56) v = *(const float4*)(state + n * 56 + k4);
        __half h0[4], h1[4];
        split2h(v.x, h0[0], h1[0]);
        split2h(v.y, h0[1], h1[1]);
        split2h(v.z, h0[2], h1[2]);
        split2h(v.w, h0[3], h1[3]);
        __half* d = spin + n * 128 + k4;
        __half2 p00; p00.x = h0[0]; p00.y = h0[1];
        __half2 p01; p01.x = h0[2]; p01.y = h0[3];
        __half2 p10; p10.x = h1[0]; p10.y = h1[1];
        __half2 p11; p11.x = h1[2]; p11.y = h1[3];
        *(__half2*)(d)          = p00;
        *(__half2*)(d + 2)      = p01;
        *(__half2*)(d + 64)     = p10;
        *(__half2*)(d + 66)     = p11;
        return;
    }
    gid -= 2097152L;
    if (gid < 131072) {
        long i4 = gid * 4;
        float4 v = *(const float4*)(cbk + i4);
        __nv_bfloat162 b0; b0.x = __float2bfloat16(v.x); b0.y = __float2bfloat16(v.y);
        __nv_bfloat162 b1; b1.x = __float2bfloat16(v.z); b1.y = __float2bfloat16(v.w);
        *(__nv_bfloat162*)(cbh + i4)     = b0;
        *(__nv_bfloat162*)(cbh + i4 + 2) = b1;
        return;
    }
    gid -= 131072;
    if (gid < 131072) {
        int k = (int)(gid / 512), m = (int)(gid % 512);
        wt1[(size_t)m * 256 + k] = __float2bfloat16(dw1[gid]);
        return;
    }
    gid -= 131072;
    if (gid < 262144) {
        int k = (int)(gid / 512), m = (int)(gid % 512);
        wt2[(size_t)m * 512 + k] = __float2bfloat16(dw2[gid]);
        return;
    }
    gid -= 262144;
    if (gid < 28672) {
        int k = (int)(gid / 56), m = (int)(gid % 56);
        wt3[(size_t)m * 512 + k] = __float2bfloat16(dw3[gid]);
        return;
    }
    gid -= 28672;
    if (gid < 32768) {
        int m = (int)(gid / 64), k = (int)(gid % 64);
        float v = (k < 56) ? ew1[(size_t)k * 512 + m] : 0.f;
        __half h0, h1; split2h(v, h0, h1);
        __half* d = wsp1 + (size_t)m * 128;
        d[k] = h0; d[64 + k] = h1;
        return;
    }
    gid -= 32768;
    if (gid < 262144) {
        int m = (int)(gid / 512), k = (int)(gid % 512);
        float v = ew2[(size_t)k * 512 + m];
        __half h0, h1; split2h(v, h0, h1);
        __half* d = wsp2 + (size_t)m * 1024;
        d[k] = h0; d[512 + k] = h1;
        return;
    }
    gid -= 262144;
    if (gid < 131072) {
        int m = (int)(gid / 512), k = (int)(gid % 512);
        float v = ew3[(size_t)k * 256 + m];
        __half h0, h1; split2h(v, h0, h1);
        __half* d = wsp3 + (size_t)m * 1024;
        d[k] = h0; d[512 + k] = h1;
        return;
    }
    gid -= 131072;
    if (gid < 65536) {
        int w = (int)(gid >> 5);
        int lane = (int)(gid & 31);
        const float* c = cbk + (size_t)w * 256;
        float s = 0.f;
        #pragma unroll
        for (int k = lane; k < 256; k += 32) s = fmaf(c[k], c[k], s);
        #pragma unroll
        for (int off = 16; off > 0; off >>= 1) s += __shfl_xor_sync(0xffffffff, s, off);
        if (lane == 0) cnp[w] = 0.5f * s;
    }
}
#define PREP_THREADS (2097152L + 131072 + 131072 + 262144 + 28672 + 32768 + 262144 + 131072 + 65536)
#define PREP_BLOCKS  ((int)((PREP_THREADS + 255) / 256))

// ================= fused residual-VQ, 512 threads (16 warps, 4x4 layout) =================
// smem layout (rel. to aligned base):
//   As 0..65536 | Bs 65536..196608 | cand 196608..212992 | rowmin 212992..213504
//   cnt 213504..214016 | ch0 214016..214528 | ch1 214528..215040 | red 215040..217088
//   s0 217088..217092
#define VQ_SMEM (217092 + 1024)
#define VQT 512

__device__ __forceinline__ void vq_score8(
    unsigned AsB, unsigned BsB, char* smc,
    const __nv_bfloat16* __restrict__ cbh, const float* __restrict__ cn,
    int* cand, unsigned* rowmin, int* cnt,
    int tid, int lane, int wid, int wm, int wn, int g, int q2, int lrow, int lcb)
{
    #pragma unroll
    for (int i = 0; i < 8; i++) {
        int ch = tid + VQT * i;
        int r = ch >> 5, gg = ch & 31;
        cpa16(BsB + (unsigned)(gg >> 3) * 16384u + SWZ(r, (gg & 7) * 16),
              cbh + (size_t)r * 256 + gg * 8, 16);
    }
    CP_COMMIT;

    for (int t = 0; t < 8; t++) {
        if (t < 7) {
            unsigned stb = BsB + (unsigned)((t + 1) & 1) * 65536u;
            #pragma unroll
            for (int i = 0; i < 8; i++) {
                int ch = tid + VQT * i;
                int r = ch >> 5, gg = ch & 31;
                cpa16(stb + (unsigned)(gg >> 3) * 16384u + SWZ(r, (gg & 7) * 16),
                      cbh + (size_t)((t + 1) * 128 + r) * 256 + gg * 8, 16);
            }
            CP_COMMIT;
            cp_wait<1>();
        } else {
            cp_wait<0>();
        }
        __syncthreads();

        float acc[2][4][4];
        #pragma unroll
        for (int a = 0; a < 2; a++)
            #pragma unroll
            for (int b = 0; b < 4; b++)
                #pragma unroll
                for (int c = 0; c < 4; c++) acc[a][b][c] = 0.f;

        const unsigned Bst = BsB + (unsigned)(t & 1) * 65536u;
        #pragma unroll
        for (int kk = 0; kk < 256; kk += 16) {
            int kb = kk >> 6;
            int kloc = (kk & 63) * 2;
            unsigned a[2][4];
            #pragma unroll
            for (int mf = 0; mf < 2; mf++) {
                int r = wm * 32 + mf * 16 + lrow;
                ldsm4(a[mf][0], a[mf][1], a[mf][2], a[mf][3],
                      AsB + (unsigned)kb * 16384u + SWZ(r, kloc + lcb));
            }
            unsigned bq[2][4];
            #pragma unroll
            for (int h = 0; h < 2; h++) {
                int r = wn * 32 + h * 16 + lrow;
                ldsm4(bq[h][0], bq[h][1], bq[h][2], bq[h][3],
                      Bst + (unsigned)kb * 16384u + SWZ(r, kloc + lcb));
            }
            #pragma unroll
            for (int nf = 0; nf < 4; nf++) {
                int h = nf >> 1, o = nf & 1;
                mma_bf16(acc[0][nf], a[0], bq[h][o], bq[h][o + 2]);
                mma_bf16(acc[1][nf], a[1], bq[h][o], bq[h][o + 2]);
            }
        }

        #pragma unroll
        for (int mf = 0; mf < 2; mf++) {
            int r1 = wm * 32 + mf * 16 + g;
            float m1 = 1e30f, m2 = 1e30f;
            #pragma unroll
            for (int nf = 0; nf < 4; nf++) {
                int cl = wn * 32 + nf * 8 + q2;
                float cn0 = __ldg(cn + t * 128 + cl);
                float cn1 = __ldg(cn + t * 128 + cl + 1);
                float s0 = cn0 - acc[mf][nf][0];
                float s1 = cn1 - acc[mf][nf][1];
                float s2 = cn0 - acc[mf][nf][2];
                float s3 = cn1 - acc[mf][nf][3];
                acc[mf][nf][0] = s0; acc[mf][nf][1] = s1;
                acc[mf][nf][2] = s2; acc[mf][nf][3] = s3;
                m1 = fminf(m1, fminf(s0, s1));
                m2 = fminf(m2, fminf(s2, s3));
            }
            atomicMin(&rowmin[r1], fford(m1));
            atomicMin(&rowmin[r1 + 8], fford(m2));
        }
        __syncthreads();
        #pragma unroll
        for (int mf = 0; mf < 2; mf++) {
            int r1 = wm * 32 + mf * 16 + g;
            float thr1 = iford(rowmin[r1]) + MARGIN;
            float thr2 = iford(rowmin[r1 + 8]) + MARGIN;
            #pragma unroll
            for (int nf = 0; nf < 4; nf++) {
                int code = t * 128 + wn * 32 + nf * 8 + q2;
                #pragma unroll
                for (int e = 0; e < 4; e++) {
                    float s = acc[mf][nf][e];
                    int r = (e >= 2) ? (r1 + 8) : r1;
                    float thr = (e >= 2) ? thr2 : thr1;
                    if (s <= thr) {
                        int p = atomicAdd(&cnt[r], 1);
                        if (p < CAND_CAP) cand[r * CAND_CAP + p] = code + (e & 1);
                    }
                }
            }
        }
        __syncthreads();
    }
}

__device__ __forceinline__ void vq_rescue(
    const float rr[8], const float* __restrict__ cbf, const float* __restrict__ cn,
    const int* cand, int row, int cv, int lane, int& bc_out)
{
    float bv = 1e30f; int bc = 0;
    if (cv <= CAND_CAP) {
        for (int i = 0; i < cv; i++) {
            int c = cand[row * CAND_CAP + i];
            const float* cp = cbf + (size_t)c * 256 + lane * 8;
            float d = 0.f;
            #pragma unroll
            for (int e = 0; e < 8; e++) d = fmaf(rr[e], __ldg(cp + e), d);
            #pragma unroll
            for (int off = 16; off > 0; off >>= 1) d += __shfl_xor_sync(0xffffffff, d, off);
            float s = __ldg(cn + c) - d;
            if (s < bv || (s == bv && c < bc)) { bv = s; bc = c; }
        }
    } else {
        for (int c = 0; c < 1024; c++) {
            const float* cp = cbf + (size_t)c * 256 + lane * 8;
            float d = 0.f;
            #pragma unroll
            for (int e = 0; e < 8; e++) d = fmaf(rr[e], __ldg(cp + e), d);
            #pragma unroll
            for (int off = 16; off > 0; off >>= 1) d += __shfl_xor_sync(0xffffffff, d, off);
            float s = __ldg(cn + c) - d;
            if (s < bv || (s == bv && c < bc)) { bv = s; bc = c; }
        }
    }
    bc_out = bc;
}

__global__ __launch_bounds__(VQT) void vqfused_k(
    const float* __restrict__ zg, const __nv_bfloat16* __restrict__ cbh,
    const float* __restrict__ cbf, const float* __restrict__ cn,
    float* __restrict__ codes_out, __nv_bfloat16* __restrict__ qbf,
    float* __restrict__ vqpart)
{
    extern __shared__ __align__(16) char sm[];
    unsigned dynb = (smaddr(sm) + 1023u) & ~1023u;
    char* smc = sm + (int)(dynb - smaddr(sm));
    const unsigned AsB = dynb;
    const unsigned BsB = dynb + 65536u;
    int*      cand   = (int*)     (smc + 196608);
    unsigned* rowmin = (unsigned*)(smc + 212992);
    int*      cnt    = (int*)     (smc + 213504);
    int*      ch0    = (int*)     (smc + 214016);
    int*      ch1    = (int*)     (smc + 214528);
    float*    red    = (float*)   (smc + 215040);
    float*    s0p    = (float*)   (smc + 217088);

    const int tid = threadIdx.x;
    const int lane = tid & 31, wid = tid >> 5;
    const int wm = wid & 3, wn = wid >> 2;          // wn 0..3 (32-col groups)
    const size_t row0 = (size_t)blockIdx.x * 128;
    const int g = lane >> 2, q2 = (lane & 3) * 2;
    const int lrow = ((lane >> 3) & 1) * 8 + (lane & 7);
    const int lcb  = (lane >= 16) ? 16 : 0;

    const __nv_bfloat16* cbh1 = cbh + 1024 * 256;
    const float* cbf1 = cbf + 1024 * 256;
    const float* cn1  = cn + 1024;

    if (tid < 128) { rowmin[tid] = 0xFFFFFFFFu; cnt[tid] = 0; }

    // A tile: fp32 z -> bf16, swizzled
    #pragma unroll
    for (int i = 0; i < 16; i++) {
        int e = tid + VQT * i;
        int r = e >> 6, c4 = e & 63;
        float4 v = *(const float4*)(zg + (row0 + r) * 256 + 4 * c4);
        __nv_bfloat162 h0; h0.x = __float2bfloat16(v.x); h0.y = __float2bfloat16(v.y);
        __nv_bfloat162 h1; h1.x = __float2bfloat16(v.z); h1.y = __float2bfloat16(v.w);
        uint2 p; p.x = *(unsigned*)&h0; p.y = *(unsigned*)&h1;
        int kb = c4 >> 4;
        unsigned off = (unsigned)kb * 16384u + (unsigned)r * 128u
                     + (((unsigned)((c4 * 8) & 127)) ^ (((unsigned)r & 7u) << 4));
        *(uint2*)(smc + off) = p;
    }
    __syncthreads();

    vq_score8(AsB, BsB, smc, cbh, cn, cand, rowmin, cnt,
              tid, lane, wid, wm, wn, g, q2, lrow, lcb);

    // rescue Q0: one warp per row, 8 rows per warp
    for (int j = 0; j < 8; j++) {
        int row = wid + 16 * j;
        const float* rp = zg + (row0 + row) * 256 + lane * 8;
        float4 u = *(const float4*)rp;
        float4 v = *(const float4*)(rp + 4);
        float rr[8] = {u.x, u.y, u.z, u.w, v.x, v.y, v.z, v.w};
        int bc;
        vq_rescue(rr, cbf, cn, cand, row, cnt[row], lane, bc);
        if (lane == 0) {
            ch0[row] = bc;
            codes_out[(row0 + row) * 2 + 0] = (float)bc;
        }
    }
    __syncthreads();

    // update 0: residual -> bf16 As (in place), commitment partial
    float vac = 0.f;
    #pragma unroll
    for (int i = 0; i < 16; i++) {
        int e = tid + VQT * i;
        int r = e >> 6, c4 = e & 63;
        int c = ch0[r];
        size_t off = (row0 + r) * 256 + 4 * c4;
        float4 cvv = *(const float4*)(cbf + (size_t)c * 256 + 4 * c4);
        float4 zv  = *(const float4*)(zg + off);
        float4 dv = make_float4(zv.x - cvv.x, zv.y - cvv.y, zv.z - cvv.z, zv.w - cvv.w);
        vac += dv.x * dv.x + dv.y * dv.y + dv.z * dv.z + dv.w * dv.w;
        __nv_bfloat162 h0; h0.x = __float2bfloat16(dv.x); h0.y = __float2bfloat16(dv.y);
        __nv_bfloat162 h1; h1.x = __float2bfloat16(dv.z); h1.y = __float2bfloat16(dv.w);
        uint2 p; p.x = *(unsigned*)&h0; p.y = *(unsigned*)&h1;
        int kb = c4 >> 4;
        unsigned soff = (unsigned)kb * 16384u + (unsigned)r * 128u
                      + (((unsigned)((c4 * 8) & 127)) ^ (((unsigned)r & 7u) << 4));
        *(uint2*)(smc + soff) = p;
    }
    red[tid] = vac;
    __syncthreads();
    #pragma unroll
    for (int off = 256; off > 0; off >>= 1) {
        if (tid < off) red[tid] += red[tid + off];
        __syncthreads();
    }
    if (tid == 0) *s0p = red[0];
    if (tid < 128) { rowmin[tid] = 0xFFFFFFFFu; cnt[tid] = 0; }
    __syncthreads();

    vq_score8(AsB, BsB, smc, cbh1, cn1, cand, rowmin, cnt,
              tid, lane, wid, wm, wn, g, q2, lrow, lcb);

    // rescue Q1: rr = z - cb0[ch0]
    for (int j = 0; j < 8; j++) {
        int row = wid + 16 * j;
        const float* rp = zg + (row0 + row) * 256 + lane * 8;
        const float* cp0 = cbf + (size_t)ch0[row] * 256 + lane * 8;
        float4 u = *(const float4*)rp;
        float4 v = *(const float4*)(rp + 4);
        float4 a = *(const float4*)cp0;
        float4 b = *(const float4*)(cp0 + 4);
        float rr[8] = {u.x - a.x, u.y - a.y, u.z - a.z, u.w - a.w,
                       v.x - b.x, v.y - b.y, v.z - b.z, v.w - b.w};
        int bc;
        vq_rescue(rr, cbf1, cn1, cand, row, cnt[row], lane, bc);
        if (lane == 0) {
            ch1[row] = bc;
            codes_out[(row0 + row) * 2 + 1] = (float)bc;
        }
    }
    __syncthreads();

    // update 1: commitment partial + qbf = bf16(cb0 + cb1)
    vac = 0.f;
    #pragma unroll
    for (int i = 0; i < 16; i++) {
        int e = tid + VQT * i;
        int r = e >> 6, c4 = e & 63;
        int c = ch1[r], c0 = ch0[r];
        size_t off = (row0 + r) * 256 + 4 * c4;
        float4 cvv = *(const float4*)(cbf1 + (size_t)c * 256 + 4 * c4);
        float4 q0v = *(const float4*)(cbf + (size_t)c0 * 256 + 4 * c4);
        float4 zv  = *(const float4*)(zg + off);
        float4 rv = make_float4(zv.x - q0v.x, zv.y - q0v.y, zv.z - q0v.z, zv.w - q0v.w);
        float4 dv = make_float4(rv.x - cvv.x, rv.y - cvv.y, rv.z - cvv.z, rv.w - cvv.w);
        vac += dv.x * dv.x + dv.y * dv.y + dv.z * dv.z + dv.w * dv.w;
        float4 sv = make_float4(q0v.x + cvv.x, q0v.y + cvv.y, q0v.z + cvv.z, q0v.w + cvv.w);
        __nv_bfloat162 h0; h0.x = __float2bfloat16(sv.x); h0.y = __float2bfloat16(sv.y);
        __nv_bfloat162 h1; h1.x = __float2bfloat16(sv.z); h1.y = __float2bfloat16(sv.w);
        *(__nv_bfloat162*)(qbf + off) = h0;
        *(__nv_bfloat162*)(qbf + off + 2) = h1;
    }
    red[tid] = vac;
    __syncthreads();
    #pragma unroll
    for (int off = 256; off > 0; off >>= 1) {
        if (tid < off) red[tid] += red[tid + off];
        __syncthreads();
    }
    if (tid == 0) vqpart[blockIdx.x] = *s0p + red[0];
}

// ================= final deterministic loss combine =================
__global__ __launch_bounds__(256) void final_k(
    const float* __restrict__ l1p, const float* __restrict__ vqp, float* __restrict__ out)
{
    __shared__ float sa[256], sb[256];
    float a = 0.f, b = 0.f;
    for (int i = threadIdx.x; i < RB128; i += 256) { a += l1p[i]; b += vqp[i]; }
    sa[threadIdx.x] = a; sb[threadIdx.x] = b;
    __syncthreads();
    #pragma unroll
    for (int off = 128; off > 0; off >>= 1) {
        if (threadIdx.x < off) {
            sa[threadIdx.x] += sa[threadIdx.x + off];
            sb[threadIdx.x] += sb[threadIdx.x + off];
        }
        __syncthreads();
    }
    if (threadIdx.x == 0) {
        float enc_loss = sa[0] / (131072.0f * 56.0f);
        float vq_loss  = sb[0] / (131072.0f * 256.0f);
        out[0] = enc_loss + 5.0f * vq_loss;
    }
}

// ================= launch =================
extern "C" void kernel_launch(void* const* d_in, const int* in_sizes, int n_in,
                              void* d_out, int out_size)
{
    const float* state = (const float*)d_in[0];
    const float* ew1 = (const float*)d_in[1];
    const float* eb1 = (const float*)d_in[2];
    const float* ew2 = (const float*)d_in[3];
    const float* eb2 = (const float*)d_in[4];
    const float* ew3 = (const float*)d_in[5];
    const float* eb3 = (const float*)d_in[6];
    const float* dw1 = (const float*)d_in[7];
    const float* db1 = (const float*)d_in[8];
    const float* dw2 = (const float*)d_in[9];
    const float* db2 = (const float*)d_in[10];
    const float* dw3 = (const float*)d_in[11];
    const float* db3 = (const float*)d_in[12];
    const float* cbk = (const float*)d_in[13];
    float* out = (float*)d_out;

    float *zb, *cnp, *l1p, *vqp;
    __nv_bfloat16 *qbf, *dbA, *dbB, *cbh, *wt1, *wt2, *wt3;
    __half *spin, *sp1, *sp2, *wsp1, *wsp2, *wsp3;
    cudaGetSymbolAddress((void**)&zb,   g_z);
    cudaGetSymbolAddress((void**)&qbf,  g_qbf);
    cudaGetSymbolAddress((void**)&dbA,  g_dbA);
    cudaGetSymbolAddress((void**)&dbB,  g_dbB);
    cudaGetSymbolAddress((void**)&spin, g_spin);
    cudaGetSymbolAddress((void**)&sp1,  g_sp1);
    cudaGetSymbolAddress((void**)&sp2,  g_sp2);
    cudaGetSymbolAddress((void**)&wsp1, g_wsp1);
    cudaGetSymbolAddress((void**)&wsp2, g_wsp2);
    cudaGetSymbolAddress((void**)&wsp3, g_wsp3);
    cudaGetSymbolAddress((void**)&wt1,  g_wt1);
    cudaGetSymbolAddress((void**)&wt2,  g_wt2);
    cudaGetSymbolAddress((void**)&wt3,  g_wt3);
    cudaGetSymbolAddress((void**)&cbh,  g_cbh);
    cudaGetSymbolAddress((void**)&cnp,  g_cn);
    cudaGetSymbolAddress((void**)&l1p,  g_l1p);
    cudaGetSymbolAddress((void**)&vqp,  g_vqp);

    const int DSM = 1024 + 3 * 32768;   // 99328
    cudaFuncSetAttribute(mgemm<64, 1, 1>,  cudaFuncAttributeMaxDynamicSharedMemorySize, DSM);
    cudaFuncSetAttribute(mgemm<512, 1, 1>, cudaFuncAttributeMaxDynamicSharedMemorySize, DSM);
    cudaFuncSetAttribute(mgemm<512, 1, 0>, cudaFuncAttributeMaxDynamicSharedMemorySize, DSM);
    cudaFuncSetAttribute(mgemm<256, 0, 2>, cudaFuncAttributeMaxDynamicSharedMemorySize, DSM);
    cudaFuncSetAttribute(mgemm<512, 0, 2>, cudaFuncAttributeMaxDynamicSharedMemorySize, DSM);
    cudaFuncSetAttribute(mgemm<512, 0, 3>, cudaFuncAttributeMaxDynamicSharedMemorySize, DSM);
    cudaFuncSetAttribute(vqfused_k, cudaFuncAttributeMaxDynamicSharedMemorySize, VQ_SMEM);

    dim3 blk(256);

    // fused prep (state split + weights + codebook; vectorized big sections)
    prep_k<<<PREP_BLOCKS, blk>>>(state, ew1, ew2, ew3, dw1, dw2, dw3, cbk,
                                 spin, wsp1, wsp2, wsp3, wt1, wt2, wt3, cbh, cnp);

    // encoder: fp16 split2 (col-fast grids)
    mgemm<64, 1, 1><<<dim3(4, RB128), blk, DSM>>>(spin, wsp1, eb1, sp1, 512, 512, nullptr, nullptr);
    mgemm<512, 1, 1><<<dim3(4, RB128), blk, DSM>>>(sp1, wsp2, eb2, sp2, 512, 512, nullptr, nullptr);
    mgemm<512, 1, 0><<<dim3(2, RB128), blk, DSM>>>(sp2, wsp3, eb3, zb, 256, 0, nullptr, nullptr);

    // fused residual VQ, 512 threads (codes exact fp32; q emitted as bf16)
    vqfused_k<<<RB128, VQT, VQ_SMEM>>>(zb, cbh, cbk, cnp, out + 1, qbf, vqp);

    // decoder in bf16 (col-fast grids)
    mgemm<256, 0, 2><<<dim3(4, RB128), blk, DSM>>>(qbf, wt1, db1, dbA, 512, 0, nullptr, nullptr);
    mgemm<512, 0, 2><<<dim3(4, RB128), blk, DSM>>>(dbA, wt2, db2, dbB, 512, 0, nullptr, nullptr);
    mgemm<512, 0, 3><<<dim3(1, RB128), blk, DSM>>>(dbB, wt3, db3, nullptr, 56, 0, state, l1p);

    final_k<<<1, 256>>>(l1p, vqp, out);
}